// round 7
// baseline (speedup 1.0000x reference)
#include <cuda_runtime.h>
#include <math.h>

#define N_NODES 40000
#define E_EDGES 200000
#define DIM 256
#define NHEAD 8
#define DKK 32
#define NODE_F (N_NODES * DIM)
#define PAD_F (64 * DIM)

// k-permutation within each 8-group: source col i -> position (i<4 ? 2i : 2i-7)
// Applied to the K dim of all GEMM operands so mma fragment pairs (c, c+4)
// are adjacent in smem -> float2 LDS, conflict-free.

// ---------------- scratch (device globals) ----------------
__device__ float g_hr[2][NODE_F + PAD_F];   // tf32-rounded, k-permuted copies of h_A, h_B
__device__ float g_Q[2][NODE_F];
__device__ float g_k[3][NODE_F];
__device__ float g_v[3][NODE_F];
__device__ float g_WT[2048 * 256];          // K-major concat weights, tf32-rounded, k-permuted
__device__ float g_bc[2048];
__device__ float g_WaT[2 * 256 * 256];      // Wa^T, K-major, tf32-rounded, k-permuted
__device__ float g_s[3][N_NODES * NHEAD];
__device__ float g_agg[3][NODE_F];
__device__ float g_tt[2][NODE_F + PAD_F];   // combined features, tf32-rounded, k-permuted

struct OutPtrs { float* p[5]; };

// ---------------- helpers ----------------
__device__ __forceinline__ unsigned tf32r(float f) {
    unsigned u;
    asm("cvt.rna.tf32.f32 %0, %1;" : "=r"(u) : "f"(f));
    return u;
}
__device__ __forceinline__ void mma_tf32(float* d, const unsigned* a, const unsigned* b) {
    asm volatile(
        "mma.sync.aligned.m16n8k8.row.col.f32.tf32.tf32.f32 "
        "{%0,%1,%2,%3}, {%4,%5,%6,%7}, {%8,%9}, {%0,%1,%2,%3};"
        : "+f"(d[0]), "+f"(d[1]), "+f"(d[2]), "+f"(d[3])
        : "r"(a[0]), "r"(a[1]), "r"(a[2]), "r"(a[3]), "r"(b[0]), "r"(b[1]));
}
__device__ __forceinline__ void cpa16(unsigned saddr, const void* g) {
    asm volatile("cp.async.cg.shared.global [%0], [%1], 16;" :: "r"(saddr), "l"(g));
}
__device__ __forceinline__ unsigned smem_u32(const void* p) {
    unsigned a;
    asm("{ .reg .u64 t; cvta.to.shared.u64 t, %1; cvt.u32.u64 %0, t; }" : "=r"(a) : "l"(p));
    return a;
}
__device__ __forceinline__ void red_add_v4(float* gaddr, float x, float y, float z, float w) {
    asm volatile("red.global.add.v4.f32 [%0], {%1,%2,%3,%4};"
                 :: "l"(gaddr), "f"(x), "f"(y), "f"(z), "f"(w) : "memory");
}

// ---------------- init: s=0, agg=0 ----------------
__global__ void init_kernel() {
    const int n_s4   = 3 * N_NODES * NHEAD / 4;
    const int n_agg4 = 3 * NODE_F / 4;
    int stride = gridDim.x * blockDim.x;
    float4 z = make_float4(0.f, 0.f, 0.f, 0.f);
    for (int i = blockIdx.x * blockDim.x + threadIdx.x; i < n_s4; i += stride)
        ((float4*)g_s)[i] = z;
    for (int i = blockIdx.x * blockDim.x + threadIdx.x; i < n_agg4; i += stride)
        ((float4*)g_agg)[i] = z;
}

// ---------------- round + permute inputs ----------------
__global__ void round_kernel(const float* __restrict__ hA, const float* __restrict__ hB) {
    int stride = gridDim.x * blockDim.x;
    const int ngrp = NODE_F / 8;
    for (int i = blockIdx.x * blockDim.x + threadIdx.x; i < ngrp; i += stride) {
        float4 lo = ((const float4*)hA)[2 * i];
        float4 hi = ((const float4*)hA)[2 * i + 1];
        uint4 o0, o1;
        o0.x = tf32r(lo.x); o0.y = tf32r(hi.x); o0.z = tf32r(lo.y); o0.w = tf32r(hi.y);
        o1.x = tf32r(lo.z); o1.y = tf32r(hi.z); o1.z = tf32r(lo.w); o1.w = tf32r(hi.w);
        ((uint4*)g_hr[0])[2 * i]     = o0;
        ((uint4*)g_hr[0])[2 * i + 1] = o1;
        lo = ((const float4*)hB)[2 * i];
        hi = ((const float4*)hB)[2 * i + 1];
        o0.x = tf32r(lo.x); o0.y = tf32r(hi.x); o0.z = tf32r(lo.y); o0.w = tf32r(hi.y);
        o1.x = tf32r(lo.z); o1.y = tf32r(hi.z); o1.z = tf32r(lo.w); o1.w = tf32r(hi.w);
        ((uint4*)g_hr[1])[2 * i]     = o0;
        ((uint4*)g_hr[1])[2 * i + 1] = o1;
    }
}

// ---------------- build transposed weights + biases + WaT (k-permuted) ----------------
#define TOTW  (2048 * 256)
#define TOTB  2048
#define TOTWA (2 * 256 * 256)
__device__ __forceinline__ int kperm(int k) {
    int i = k & 7;
    return (k & ~7) + ((i < 4) ? 2 * i : 2 * i - 7);
}
__global__ void build_all(const float* __restrict__ Wq, const float* __restrict__ bq,
                          const float* __restrict__ Wk, const float* __restrict__ bk,
                          const float* __restrict__ Wv, const float* __restrict__ bv,
                          const float* __restrict__ Wa,
                          const float* __restrict__ rel_att, const float* __restrict__ rel_msg) {
    int gid = blockIdx.x * blockDim.x + threadIdx.x;
    if (gid < TOTW) {
        int k = gid & 255;
        int n = gid >> 8;
        int side  = (n < 1280) ? 0 : 1;
        int local = side ? (n - 1280) : n;
        int g = local >> 8, col = local & 255;
        float val;
        if (g == 0) {
            val = Wq[side * 65536 + k * 256 + col];
        } else {
            int r   = side ? 1 : ((g <= 2) ? 0 : 2);
            int isv = side ? (g == 2) : ((g & 1) == 0);
            const float* W  = (isv ? Wv : Wk) + side * 65536 + k * 256 + (col >> 5) * 32;
            const float* rp = (isv ? rel_msg : rel_att) + r * 8192 + (col >> 5) * 1024 + (col & 31);
            float acc = 0.f;
            #pragma unroll
            for (int d = 0; d < 32; d++) acc += W[d] * rp[d * 32];
            val = acc;
        }
        g_WT[n * 256 + kperm(k)] = __uint_as_float(tf32r(val));
    } else if (gid < TOTW + TOTB) {
        int n = gid - TOTW;
        int side  = (n < 1280) ? 0 : 1;
        int local = side ? (n - 1280) : n;
        int g = local >> 8, col = local & 255;
        float val;
        if (g == 0) {
            val = bq[side * 256 + col];
        } else {
            int r   = side ? 1 : ((g <= 2) ? 0 : 2);
            int isv = side ? (g == 2) : ((g & 1) == 0);
            const float* b  = (isv ? bv : bk) + side * 256 + (col >> 5) * 32;
            const float* rp = (isv ? rel_msg : rel_att) + r * 8192 + (col >> 5) * 1024 + (col & 31);
            float acc = 0.f;
            #pragma unroll
            for (int d = 0; d < 32; d++) acc += b[d] * rp[d * 32];
            val = acc;
        }
        g_bc[n] = val;
    } else if (gid < TOTW + TOTB + TOTWA) {
        int i = gid - TOTW - TOTB;
        int k = i & 255, nn = (i >> 8) & 255, t = i >> 16;
        g_WaT[t * 65536 + nn * 256 + kperm(k)] = __uint_as_float(tf32r(Wa[t * 65536 + k * 256 + nn]));
    }
}

// ---------------- tf32 mma.sync GEMM, cp.async 4-stage (K=16 half-chunks) ----------------
// CTA tile 128x128, warp tile 64x32 (2x4 warps), 16 half-chunks, smem row stride 24
#define SSTR 24
#define STG_FLOATS 6144           // per stage: A(3072) + B(3072)
#define STG_BYTES 24576u
#define TG_SMEM 98304
#define NHC 16
__global__ void __launch_bounds__(256, 2) tgemm(
        const float* __restrict__ A, const float* __restrict__ WT,
        const float* __restrict__ bias, OutPtrs outs, int M,
        int mode, const float* __restrict__ skipv, const float* __restrict__ Hres) {
    extern __shared__ float smem[];
    unsigned sbase = smem_u32(smem);
    int tid = threadIdx.x, lane = tid & 31, wid = tid >> 5;
    int row0 = blockIdx.y * 128;
    int col0 = blockIdx.x * 128;
    int wm = (wid >> 2) * 64;
    int wn = (wid & 3) * 32;
    int g = lane >> 2, c = lane & 3;

    // staging: per operand per half-chunk = 512 float4; thread covers rows rs, rs+64 at jc
    int rs = tid >> 2, jc = tid & 3;
    const float* Ab0 = A  + (size_t)(row0 + rs)      * 256 + jc * 4;
    const float* Ab1 = A  + (size_t)(row0 + rs + 64) * 256 + jc * 4;
    const float* Bb0 = WT + (size_t)(col0 + rs)      * 256 + jc * 4;
    const float* Bb1 = WT + (size_t)(col0 + rs + 64) * 256 + jc * 4;
    unsigned soA0 = (unsigned)(rs * SSTR + jc * 4) * 4u;
    unsigned soA1 = (unsigned)((rs + 64) * SSTR + jc * 4) * 4u;

    float acc[4][4][4];
    #pragma unroll
    for (int i = 0; i < 4; i++)
        #pragma unroll
        for (int j = 0; j < 4; j++)
            #pragma unroll
            for (int q = 0; q < 4; q++) acc[i][j][q] = 0.f;

    // prefetch half-chunks 0..2 into stages 0..2
    #pragma unroll
    for (int pc = 0; pc < 3; pc++) {
        unsigned stb = sbase + pc * STG_BYTES;
        cpa16(stb + soA0,           Ab0 + pc * 16);
        cpa16(stb + soA1,           Ab1 + pc * 16);
        cpa16(stb + 12288u + soA0,  Bb0 + pc * 16);
        cpa16(stb + 12288u + soA1,  Bb1 + pc * 16);
        asm volatile("cp.async.commit_group;" ::: "memory");
    }

    #pragma unroll
    for (int ck = 0; ck < NHC; ck++) {
        if (ck <= 13)      asm volatile("cp.async.wait_group 2;" ::: "memory");
        else if (ck == 14) asm volatile("cp.async.wait_group 1;" ::: "memory");
        else               asm volatile("cp.async.wait_group 0;" ::: "memory");
        __syncthreads();
        if (ck + 3 < NHC) {
            unsigned stb = sbase + ((ck + 3) & 3) * STG_BYTES;
            cpa16(stb + soA0,          Ab0 + (ck + 3) * 16);
            cpa16(stb + soA1,          Ab1 + (ck + 3) * 16);
            cpa16(stb + 12288u + soA0, Bb0 + (ck + 3) * 16);
            cpa16(stb + 12288u + soA1, Bb1 + (ck + 3) * 16);
            asm volatile("cp.async.commit_group;" ::: "memory");
        }
        const float* sA = smem + (ck & 3) * STG_FLOATS;
        const float* sB = sA + 3072;
        #pragma unroll
        for (int s = 0; s < 2; s++) {
            unsigned af[4][4], bf[4][2];
            int kc = s * 8 + 2 * c;
            #pragma unroll
            for (int mt = 0; mt < 4; mt++) {
                int m = wm + mt * 16;
                float2 lo = *(const float2*)&sA[(m + g)     * SSTR + kc];
                float2 hi = *(const float2*)&sA[(m + g + 8) * SSTR + kc];
                af[mt][0] = __float_as_uint(lo.x);
                af[mt][1] = __float_as_uint(hi.x);
                af[mt][2] = __float_as_uint(lo.y);
                af[mt][3] = __float_as_uint(hi.y);
            }
            #pragma unroll
            for (int nt = 0; nt < 4; nt++) {
                float2 b = *(const float2*)&sB[(wn + nt * 8 + g) * SSTR + kc];
                bf[nt][0] = __float_as_uint(b.x);
                bf[nt][1] = __float_as_uint(b.y);
            }
            #pragma unroll
            for (int mt = 0; mt < 4; mt++)
                #pragma unroll
                for (int nt = 0; nt < 4; nt++)
                    mma_tf32(acc[mt][nt], af[mt], bf[nt]);
        }
    }

    // epilogue
    float alpha = 1.f, beta = 0.f;
    if (mode == 1) {
        float sv = *skipv;
        alpha = 1.f / (1.f + __expf(-sv));
        beta  = 1.f - alpha;
    }
    float* Cg = outs.p[blockIdx.x >> 1];
    int cinb = (col0 & 255) + wn;
    #pragma unroll
    for (int mt = 0; mt < 4; mt++) {
        #pragma unroll
        for (int half = 0; half < 2; half++) {
            int row = row0 + wm + mt * 16 + g + half * 8;
            if (row >= M) continue;
            #pragma unroll
            for (int nt = 0; nt < 4; nt++) {
                int cin = cinb + nt * 8 + 2 * c;
                float v0 = acc[mt][nt][half * 2 + 0] + bias[col0 + wn + nt * 8 + 2 * c];
                float v1 = acc[mt][nt][half * 2 + 1] + bias[col0 + wn + nt * 8 + 2 * c + 1];
                if (mode == 1) {
                    v0 = v0 * alpha + Hres[(size_t)row * 256 + cin]     * beta;
                    v1 = v1 * alpha + Hres[(size_t)row * 256 + cin + 1] * beta;
                }
                float2 o; o.x = v0; o.y = v1;
                *(float2*)(Cg + (size_t)row * 256 + cin) = o;
            }
        }
    }
}

// ---------------- fused edge pass: score + exp + sum + scatter ----------------
__global__ void edge_fused(const float* __restrict__ Q, const float* __restrict__ K,
                           const float* __restrict__ V,
                           const int* __restrict__ src, const int* __restrict__ dst,
                           const float* __restrict__ pri,
                           float* __restrict__ s, float* __restrict__ agg, int E) {
    int e = blockIdx.x * (blockDim.x >> 5) + (threadIdx.x >> 5);
    int lane = threadIdx.x & 31;
    if (e >= E) return;
    int sn = src[e], dn = dst[e];
    const float4* q = (const float4*)(Q + (size_t)dn * DIM);
    const float4* k = (const float4*)(K + (size_t)sn * DIM);
    float4 q0 = q[lane], k0 = k[lane], q1 = q[lane + 32], k1 = k[lane + 32];
    float p0 = q0.x * k0.x + q0.y * k0.y + q0.z * k0.z + q0.w * k0.w;
    float p1 = q1.x * k1.x + q1.y * k1.y + q1.z * k1.z + q1.w * k1.w;
    #pragma unroll
    for (int off = 4; off >= 1; off >>= 1) {
        p0 += __shfl_xor_sync(0xffffffffu, p0, off);
        p1 += __shfl_xor_sync(0xffffffffu, p1, off);
    }
    float ex0 = 0.f, ex1 = 0.f;
    if ((lane & 7) == 0) {
        const float rs = 0.17677669529663687f;   // 1/sqrt(32)
        int h = lane >> 3;
        ex0 = __expf(p0 * pri[h] * rs);
        ex1 = __expf(p1 * pri[h + 4] * rs);
        atomicAdd(&s[dn * NHEAD + h],     ex0);
        atomicAdd(&s[dn * NHEAD + h + 4], ex1);
    }
    int sl = (lane >> 3) * 8;
    float e0 = __shfl_sync(0xffffffffu, ex0, sl);
    float e1 = __shfl_sync(0xffffffffu, ex1, sl);
    const float4* vrow = (const float4*)(V + (size_t)sn * DIM);
    float* arow = agg + (size_t)dn * DIM;
    float4 v0 = vrow[lane], v1 = vrow[lane + 32];
    red_add_v4(arow + lane * 4,        e0 * v0.x, e0 * v0.y, e0 * v0.z, e0 * v0.w);
    red_add_v4(arow + (lane + 32) * 4, e1 * v1.x, e1 * v1.y, e1 * v1.z, e1 * v1.w);
}

// ---------------- combine: normalize + mean + tf32 round + k-permute ----------------
__global__ void combine_kernel() {
    int j = blockIdx.x * blockDim.x + threadIdx.x;
    if (j >= NODE_F / 8) return;
    int n = j >> 5;
    int h = (j & 31) >> 2;
    float s1 = g_s[1][n * NHEAD + h];
    float s2 = g_s[2][n * NHEAD + h];
    float r1 = (s1 > 0.f) ? 0.5f / s1 : 0.f;
    float r2 = (s2 > 0.f) ? 0.5f / s2 : 0.f;
    float4 a1l = ((const float4*)g_agg[1])[2 * j];
    float4 a1h = ((const float4*)g_agg[1])[2 * j + 1];
    float4 a2l = ((const float4*)g_agg[2])[2 * j];
    float4 a2h = ((const float4*)g_agg[2])[2 * j + 1];
    float c0 = a1l.x * r1 + a2l.x * r2, c1 = a1l.y * r1 + a2l.y * r2;
    float c2 = a1l.z * r1 + a2l.z * r2, c3 = a1l.w * r1 + a2l.w * r2;
    float c4 = a1h.x * r1 + a2h.x * r2, c5 = a1h.y * r1 + a2h.y * r2;
    float c6 = a1h.z * r1 + a2h.z * r2, c7 = a1h.w * r1 + a2h.w * r2;
    uint4 o0, o1;   // permuted order: 0,4,1,5 | 2,6,3,7
    o0.x = tf32r(c0); o0.y = tf32r(c4); o0.z = tf32r(c1); o0.w = tf32r(c5);
    o1.x = tf32r(c2); o1.y = tf32r(c6); o1.z = tf32r(c3); o1.w = tf32r(c7);
    ((uint4*)g_tt[0])[2 * j]     = o0;
    ((uint4*)g_tt[0])[2 * j + 1] = o1;

    float s0 = g_s[0][n * NHEAD + h];
    float r0 = (s0 > 0.f) ? 1.f / s0 : 0.f;
    float4 a0l = ((const float4*)g_agg[0])[2 * j];
    float4 a0h = ((const float4*)g_agg[0])[2 * j + 1];
    o0.x = tf32r(a0l.x * r0); o0.y = tf32r(a0h.x * r0);
    o0.z = tf32r(a0l.y * r0); o0.w = tf32r(a0h.y * r0);
    o1.x = tf32r(a0l.z * r0); o1.y = tf32r(a0h.z * r0);
    o1.z = tf32r(a0l.w * r0); o1.w = tf32r(a0h.w * r0);
    ((uint4*)g_tt[1])[2 * j]     = o0;
    ((uint4*)g_tt[1])[2 * j + 1] = o1;
}

// ---------------- launch ----------------
extern "C" void kernel_launch(void* const* d_in, const int* in_sizes, int n_in,
                              void* d_out, int out_size) {
    const float* h_A     = (const float*)d_in[0];
    const float* h_B     = (const float*)d_in[1];
    const float* Wk      = (const float*)d_in[2];
    const float* bk      = (const float*)d_in[3];
    const float* Wq      = (const float*)d_in[4];
    const float* bq      = (const float*)d_in[5];
    const float* Wv      = (const float*)d_in[6];
    const float* bv      = (const float*)d_in[7];
    const float* Wa      = (const float*)d_in[8];
    const float* ba      = (const float*)d_in[9];
    const float* rel_att = (const float*)d_in[10];
    const float* rel_msg = (const float*)d_in[11];
    const float* rel_pri = (const float*)d_in[12];
    const float* skip    = (const float*)d_in[13];
    const int*   src[3]  = {(const int*)d_in[14], (const int*)d_in[16], (const int*)d_in[18]};
    const int*   dst[3]  = {(const int*)d_in[15], (const int*)d_in[17], (const int*)d_in[19]};
    const int E = in_sizes[14];
    float* out = (float*)d_out;

    float *pHr[2], *pQ0, *pQ1, *pk[3], *pv[3], *ps[3], *pagg[3], *ptt[2];
    float *pWT, *pbc, *pWaT;
    {
        float* base;
        cudaGetSymbolAddress((void**)&base, g_hr);  pHr[0] = base; pHr[1] = base + NODE_F + PAD_F;
        cudaGetSymbolAddress((void**)&base, g_Q);   pQ0 = base; pQ1 = base + NODE_F;
        cudaGetSymbolAddress((void**)&base, g_k);   for (int r = 0; r < 3; r++) pk[r] = base + (size_t)r * NODE_F;
        cudaGetSymbolAddress((void**)&base, g_v);   for (int r = 0; r < 3; r++) pv[r] = base + (size_t)r * NODE_F;
        cudaGetSymbolAddress((void**)&pWT,  g_WT);
        cudaGetSymbolAddress((void**)&pbc,  g_bc);
        cudaGetSymbolAddress((void**)&pWaT, g_WaT);
        cudaGetSymbolAddress((void**)&base, g_s);   for (int r = 0; r < 3; r++) ps[r] = base + (size_t)r * N_NODES * NHEAD;
        cudaGetSymbolAddress((void**)&base, g_agg); for (int r = 0; r < 3; r++) pagg[r] = base + (size_t)r * NODE_F;
        cudaGetSymbolAddress((void**)&base, g_tt);  ptt[0] = base; ptt[1] = base + NODE_F + PAD_F;
    }

    cudaFuncSetAttribute(tgemm, cudaFuncAttributeMaxDynamicSharedMemorySize, TG_SMEM);

    init_kernel<<<1024, 256>>>();
    round_kernel<<<1024, 256>>>(h_A, h_B);
    {
        int tot = TOTW + TOTB + TOTWA;
        build_all<<<(tot + 255) / 256, 256>>>(Wq, bq, Wk, bk, Wv, bv, Wa, rel_att, rel_msg);
    }

    int mblocks = (N_NODES + 127) / 128;

    // A-side fused projection: [40000 x 1280] -> Q0 | k0 | v0 | k2 | v2
    {
        OutPtrs o; o.p[0] = pQ0; o.p[1] = pk[0]; o.p[2] = pv[0]; o.p[3] = pk[2]; o.p[4] = pv[2];
        dim3 grid(10, mblocks);
        tgemm<<<grid, 256, TG_SMEM>>>(pHr[0], pWT, pbc, o, N_NODES, 0, nullptr, nullptr);
    }
    // B-side fused projection: [40000 x 768] -> Q1 | k1 | v1
    {
        OutPtrs o; o.p[0] = pQ1; o.p[1] = pk[1]; o.p[2] = pv[1]; o.p[3] = nullptr; o.p[4] = nullptr;
        dim3 grid(6, mblocks);
        tgemm<<<grid, 256, TG_SMEM>>>(pHr[1], pWT + 1280 * 256, pbc + 1280, o, N_NODES, 0, nullptr, nullptr);
    }

    // fused edge passes; Q of dst type: r0->B(1), r1->A(0), r2->A(0)
    float* Qdst[3] = {pQ1, pQ0, pQ0};
    int eblocks = (E + 7) / 8;
    for (int r = 0; r < 3; r++) {
        edge_fused<<<eblocks, 256>>>(Qdst[r], pk[r], pv[r], src[r], dst[r],
                                     rel_pri + r * NHEAD, ps[r], pagg[r], E);
    }

    combine_kernel<<<(NODE_F / 8 + 255) / 256, 256>>>();

    // output GEMMs with fused skip epilogue
    {
        dim3 grid(2, mblocks);
        OutPtrs o; o.p[0] = out; o.p[1] = o.p[2] = o.p[3] = o.p[4] = nullptr;
        tgemm<<<grid, 256, TG_SMEM>>>(ptt[0], pWaT, ba, o, N_NODES, 1, skip, h_A);
        OutPtrs o2; o2.p[0] = out + NODE_F; o2.p[1] = o2.p[2] = o2.p[3] = o2.p[4] = nullptr;
        tgemm<<<grid, 256, TG_SMEM>>>(ptt[1], pWaT + 65536, ba + 256, o2, N_NODES, 1, skip + 1, h_B);
    }
}

// round 8
// speedup vs baseline: 1.0470x; 1.0470x over previous
#include <cuda_runtime.h>
#include <math.h>

#define N_NODES 40000
#define E_EDGES 200000
#define DIM 256
#define NHEAD 8
#define NODE_F (N_NODES * DIM)
#define PAD_F (64 * DIM)
#define NSEG (3 * N_NODES)          // 120000 (relation, dst) segments

// ---------------- scratch (device globals) ----------------
__device__ float g_hr[2][NODE_F + PAD_F];   // tf32-rounded, k-permuted h_A, h_B
__device__ float g_Q[2][NODE_F];
__device__ float g_k[3][NODE_F];
__device__ float g_v[3][NODE_F];
__device__ float g_WT[2048 * 256];
__device__ float g_bc[2048];
__device__ float g_WaT[2 * 256 * 256];
__device__ float g_agg[3][NODE_F];          // normalized per-relation aggregation
__device__ float g_tt[2][NODE_F + PAD_F];
__device__ int   g_hist[NSEG];
__device__ int   g_rowptr[NSEG + 1];
__device__ int   g_cursor[NSEG];
__device__ int   g_bsum[512];
__device__ int   g_csr[3 * E_EDGES];

struct OutPtrs { float* p[5]; };
struct EdgePtrs { const float* Q[3]; const float* K[3]; const float* V[3]; float* agg[3]; };

// ---------------- helpers ----------------
__device__ __forceinline__ unsigned tf32r(float f) {
    unsigned u;
    asm("cvt.rna.tf32.f32 %0, %1;" : "=r"(u) : "f"(f));
    return u;
}
__device__ __forceinline__ void mma_tf32(float* d, const unsigned* a, const unsigned* b) {
    asm volatile(
        "mma.sync.aligned.m16n8k8.row.col.f32.tf32.tf32.f32 "
        "{%0,%1,%2,%3}, {%4,%5,%6,%7}, {%8,%9}, {%0,%1,%2,%3};"
        : "+f"(d[0]), "+f"(d[1]), "+f"(d[2]), "+f"(d[3])
        : "r"(a[0]), "r"(a[1]), "r"(a[2]), "r"(a[3]), "r"(b[0]), "r"(b[1]));
}
__device__ __forceinline__ void cpa16(unsigned saddr, const void* g) {
    asm volatile("cp.async.cg.shared.global [%0], [%1], 16;" :: "r"(saddr), "l"(g));
}
__device__ __forceinline__ unsigned smem_u32(const void* p) {
    unsigned a;
    asm("{ .reg .u64 t; cvta.to.shared.u64 t, %1; cvt.u32.u64 %0, t; }" : "=r"(a) : "l"(p));
    return a;
}

// ---------------- init: hist=0 ----------------
__global__ void init_kernel() {
    int i = blockIdx.x * blockDim.x + threadIdx.x;
    if (i < NSEG) g_hist[i] = 0;
}

// ---------------- round + permute inputs ----------------
__global__ void round_kernel(const float* __restrict__ hA, const float* __restrict__ hB) {
    int stride = gridDim.x * blockDim.x;
    const int ngrp = NODE_F / 8;
    for (int i = blockIdx.x * blockDim.x + threadIdx.x; i < ngrp; i += stride) {
        float4 lo = ((const float4*)hA)[2 * i];
        float4 hi = ((const float4*)hA)[2 * i + 1];
        uint4 o0, o1;
        o0.x = tf32r(lo.x); o0.y = tf32r(hi.x); o0.z = tf32r(lo.y); o0.w = tf32r(hi.y);
        o1.x = tf32r(lo.z); o1.y = tf32r(hi.z); o1.z = tf32r(lo.w); o1.w = tf32r(hi.w);
        ((uint4*)g_hr[0])[2 * i]     = o0;
        ((uint4*)g_hr[0])[2 * i + 1] = o1;
        lo = ((const float4*)hB)[2 * i];
        hi = ((const float4*)hB)[2 * i + 1];
        o0.x = tf32r(lo.x); o0.y = tf32r(hi.x); o0.z = tf32r(lo.y); o0.w = tf32r(hi.y);
        o1.x = tf32r(lo.z); o1.y = tf32r(hi.z); o1.z = tf32r(lo.w); o1.w = tf32r(hi.w);
        ((uint4*)g_hr[1])[2 * i]     = o0;
        ((uint4*)g_hr[1])[2 * i + 1] = o1;
    }
}

// ---------------- build transposed weights + biases + WaT (k-permuted) ----------------
#define TOTW  (2048 * 256)
#define TOTB  2048
#define TOTWA (2 * 256 * 256)
__device__ __forceinline__ int kperm(int k) {
    int i = k & 7;
    return (k & ~7) + ((i < 4) ? 2 * i : 2 * i - 7);
}
__global__ void build_all(const float* __restrict__ Wq, const float* __restrict__ bq,
                          const float* __restrict__ Wk, const float* __restrict__ bk,
                          const float* __restrict__ Wv, const float* __restrict__ bv,
                          const float* __restrict__ Wa,
                          const float* __restrict__ rel_att, const float* __restrict__ rel_msg) {
    int gid = blockIdx.x * blockDim.x + threadIdx.x;
    if (gid < TOTW) {
        int k = gid & 255;
        int n = gid >> 8;
        int side  = (n < 1280) ? 0 : 1;
        int local = side ? (n - 1280) : n;
        int g = local >> 8, col = local & 255;
        float val;
        if (g == 0) {
            val = Wq[side * 65536 + k * 256 + col];
        } else {
            int r   = side ? 1 : ((g <= 2) ? 0 : 2);
            int isv = side ? (g == 2) : ((g & 1) == 0);
            const float* W  = (isv ? Wv : Wk) + side * 65536 + k * 256 + (col >> 5) * 32;
            const float* rp = (isv ? rel_msg : rel_att) + r * 8192 + (col >> 5) * 1024 + (col & 31);
            float acc = 0.f;
            #pragma unroll
            for (int d = 0; d < 32; d++) acc += W[d] * rp[d * 32];
            val = acc;
        }
        g_WT[n * 256 + kperm(k)] = __uint_as_float(tf32r(val));
    } else if (gid < TOTW + TOTB) {
        int n = gid - TOTW;
        int side  = (n < 1280) ? 0 : 1;
        int local = side ? (n - 1280) : n;
        int g = local >> 8, col = local & 255;
        float val;
        if (g == 0) {
            val = bq[side * 256 + col];
        } else {
            int r   = side ? 1 : ((g <= 2) ? 0 : 2);
            int isv = side ? (g == 2) : ((g & 1) == 0);
            const float* b  = (isv ? bv : bk) + side * 256 + (col >> 5) * 32;
            const float* rp = (isv ? rel_msg : rel_att) + r * 8192 + (col >> 5) * 1024 + (col & 31);
            float acc = 0.f;
            #pragma unroll
            for (int d = 0; d < 32; d++) acc += b[d] * rp[d * 32];
            val = acc;
        }
        g_bc[n] = val;
    } else if (gid < TOTW + TOTB + TOTWA) {
        int i = gid - TOTW - TOTB;
        int k = i & 255, nn = (i >> 8) & 255, t = i >> 16;
        g_WaT[t * 65536 + nn * 256 + kperm(k)] = __uint_as_float(tf32r(Wa[t * 65536 + k * 256 + nn]));
    }
}

// ---------------- tf32 mma.sync GEMM (R6 proven config) ----------------
#define SSTR 40
#define STG_FLOATS 10240
#define STG_BYTES 40960u
#define TG_SMEM 81920
__global__ void __launch_bounds__(256, 2) tgemm(
        const float* __restrict__ A, const float* __restrict__ WT,
        const float* __restrict__ bias, OutPtrs outs, int M,
        int mode, const float* __restrict__ skipv, const float* __restrict__ Hres) {
    extern __shared__ float smem[];
    unsigned sbase = smem_u32(smem);
    int tid = threadIdx.x, lane = tid & 31, wid = tid >> 5;
    int row0 = blockIdx.y * 128;
    int col0 = blockIdx.x * 128;
    int wm = (wid >> 2) * 64;
    int wn = (wid & 3) * 32;
    int g = lane >> 2, c = lane & 3;

    int r_st[4], jc_st[4];
    #pragma unroll
    for (int i = 0; i < 4; i++) {
        int l = i * 256 + tid;
        r_st[i] = l >> 3; jc_st[i] = l & 7;
    }

    float acc[4][4][4];
    #pragma unroll
    for (int i = 0; i < 4; i++)
        #pragma unroll
        for (int j = 0; j < 4; j++)
            #pragma unroll
            for (int q = 0; q < 4; q++) acc[i][j][q] = 0.f;

    #pragma unroll
    for (int i = 0; i < 4; i++) {
        unsigned so = sbase + (unsigned)(r_st[i] * SSTR + jc_st[i] * 4) * 4u;
        cpa16(so, A + (size_t)(row0 + r_st[i]) * 256 + jc_st[i] * 4);
        cpa16(so + 20480u, WT + (size_t)(col0 + r_st[i]) * 256 + jc_st[i] * 4);
    }
    asm volatile("cp.async.commit_group;" ::: "memory");

    #pragma unroll
    for (int ck = 0; ck < 8; ck++) {
        asm volatile("cp.async.wait_group 0;" ::: "memory");
        __syncthreads();
        if (ck + 1 < 8) {
            unsigned stb = sbase + ((ck + 1) & 1) * STG_BYTES;
            #pragma unroll
            for (int i = 0; i < 4; i++) {
                unsigned so = stb + (unsigned)(r_st[i] * SSTR + jc_st[i] * 4) * 4u;
                cpa16(so, A + (size_t)(row0 + r_st[i]) * 256 + (ck + 1) * 32 + jc_st[i] * 4);
                cpa16(so + 20480u, WT + (size_t)(col0 + r_st[i]) * 256 + (ck + 1) * 32 + jc_st[i] * 4);
            }
            asm volatile("cp.async.commit_group;" ::: "memory");
        }
        const float* sA = smem + (ck & 1) * STG_FLOATS;
        const float* sB = sA + 5120;
        #pragma unroll
        for (int s = 0; s < 4; s++) {
            unsigned af[4][4], bf[4][2];
            int kc = s * 8 + 2 * c;
            #pragma unroll
            for (int mt = 0; mt < 4; mt++) {
                int m = wm + mt * 16;
                float2 lo = *(const float2*)&sA[(m + g)     * SSTR + kc];
                float2 hi = *(const float2*)&sA[(m + g + 8) * SSTR + kc];
                af[mt][0] = __float_as_uint(lo.x);
                af[mt][1] = __float_as_uint(hi.x);
                af[mt][2] = __float_as_uint(lo.y);
                af[mt][3] = __float_as_uint(hi.y);
            }
            #pragma unroll
            for (int nt = 0; nt < 4; nt++) {
                float2 b = *(const float2*)&sB[(wn + nt * 8 + g) * SSTR + kc];
                bf[nt][0] = __float_as_uint(b.x);
                bf[nt][1] = __float_as_uint(b.y);
            }
            #pragma unroll
            for (int mt = 0; mt < 4; mt++)
                #pragma unroll
                for (int nt = 0; nt < 4; nt++)
                    mma_tf32(acc[mt][nt], af[mt], bf[nt]);
        }
    }

    float alpha = 1.f, beta = 0.f;
    if (mode == 1) {
        float sv = *skipv;
        alpha = 1.f / (1.f + __expf(-sv));
        beta  = 1.f - alpha;
    }
    float* Cg = outs.p[blockIdx.x >> 1];
    int cinb = (col0 & 255) + wn;
    #pragma unroll
    for (int mt = 0; mt < 4; mt++) {
        #pragma unroll
        for (int half = 0; half < 2; half++) {
            int row = row0 + wm + mt * 16 + g + half * 8;
            if (row >= M) continue;
            #pragma unroll
            for (int nt = 0; nt < 4; nt++) {
                int cin = cinb + nt * 8 + 2 * c;
                float v0 = acc[mt][nt][half * 2 + 0] + bias[col0 + wn + nt * 8 + 2 * c];
                float v1 = acc[mt][nt][half * 2 + 1] + bias[col0 + wn + nt * 8 + 2 * c + 1];
                if (mode == 1) {
                    v0 = v0 * alpha + Hres[(size_t)row * 256 + cin]     * beta;
                    v1 = v1 * alpha + Hres[(size_t)row * 256 + cin + 1] * beta;
                }
                float2 o; o.x = v0; o.y = v1;
                *(float2*)(Cg + (size_t)row * 256 + cin) = o;
            }
        }
    }
}

// ---------------- CSR build: histogram -> scan -> scatter ----------------
__global__ void hist_kernel(const int* __restrict__ d0, const int* __restrict__ d1,
                            const int* __restrict__ d2, int E) {
    int i = blockIdx.x * blockDim.x + threadIdx.x;
    if (i >= 3 * E) return;
    int r = i / E, e = i - r * E;
    const int* dd = (r == 0) ? d0 : ((r == 1) ? d1 : d2);
    atomicAdd(&g_hist[r * N_NODES + dd[e]], 1);
}
__global__ void scan1() {               // per-block sums (469 blocks x 256)
    __shared__ int sh[256];
    int i = blockIdx.x * 256 + threadIdx.x;
    sh[threadIdx.x] = (i < NSEG) ? g_hist[i] : 0;
    __syncthreads();
    for (int o = 128; o > 0; o >>= 1) {
        if (threadIdx.x < o) sh[threadIdx.x] += sh[threadIdx.x + o];
        __syncthreads();
    }
    if (threadIdx.x == 0) g_bsum[blockIdx.x] = sh[0];
}
__global__ void scan2() {               // serial exclusive scan of block sums
    if (threadIdx.x == 0) {
        int a = 0;
        for (int b = 0; b < 469; b++) { int t = g_bsum[b]; g_bsum[b] = a; a += t; }
        g_rowptr[NSEG] = a;
    }
}
__global__ void scan3() {               // block scan + offset -> rowptr, cursor
    __shared__ int sh[256];
    int i = blockIdx.x * 256 + threadIdx.x;
    int v = (i < NSEG) ? g_hist[i] : 0;
    sh[threadIdx.x] = v;
    __syncthreads();
    for (int o = 1; o < 256; o <<= 1) {
        int t = (threadIdx.x >= (unsigned)o) ? sh[threadIdx.x - o] : 0;
        __syncthreads();
        sh[threadIdx.x] += t;
        __syncthreads();
    }
    int excl = sh[threadIdx.x] - v + g_bsum[blockIdx.x];
    if (i < NSEG) { g_rowptr[i] = excl; g_cursor[i] = excl; }
}
__global__ void scatter_kernel(const int* __restrict__ s0, const int* __restrict__ d0,
                               const int* __restrict__ s1, const int* __restrict__ d1,
                               const int* __restrict__ s2, const int* __restrict__ d2, int E) {
    int i = blockIdx.x * blockDim.x + threadIdx.x;
    if (i >= 3 * E) return;
    int r = i / E, e = i - r * E;
    const int* ss = (r == 0) ? s0 : ((r == 1) ? s1 : s2);
    const int* dd = (r == 0) ? d0 : ((r == 1) ? d1 : d2);
    int pos = atomicAdd(&g_cursor[r * N_NODES + dd[e]], 1);
    g_csr[pos] = ss[e];
}

// ---------------- edge aggregation: one warp per (relation, dst) ----------------
__global__ void agg_kernel(EdgePtrs ep, const float* __restrict__ rel_pri) {
    int gw = (blockIdx.x * blockDim.x + threadIdx.x) >> 5;
    int lane = threadIdx.x & 31;
    if (gw >= NSEG) return;
    int r = gw / N_NODES, n = gw - r * N_NODES;
    const float* Q = ep.Q[r];
    const float* K = ep.K[r];
    const float* V = ep.V[r];
    const float rs = 0.17677669529663687f;   // 1/sqrt(32)
    float pr0 = rel_pri[r * NHEAD + (lane >> 3)] * rs;
    float pr1 = rel_pri[r * NHEAD + (lane >> 3) + 4] * rs;
    int beg = g_rowptr[gw], end = g_rowptr[gw + 1];
    const float4* qr = (const float4*)(Q + (size_t)n * DIM);
    float4 q0 = qr[lane], q1 = qr[lane + 32];
    float4 a0 = make_float4(0.f, 0.f, 0.f, 0.f);
    float4 a1 = make_float4(0.f, 0.f, 0.f, 0.f);
    float ssum0 = 0.f, ssum1 = 0.f;
    for (int i = beg; i < end; i++) {
        int sn = g_csr[i];
        const float4* kr = (const float4*)(K + (size_t)sn * DIM);
        float4 k0 = kr[lane], k1 = kr[lane + 32];
        float p0 = q0.x * k0.x + q0.y * k0.y + q0.z * k0.z + q0.w * k0.w;
        float p1 = q1.x * k1.x + q1.y * k1.y + q1.z * k1.z + q1.w * k1.w;
        #pragma unroll
        for (int off = 4; off >= 1; off >>= 1) {
            p0 += __shfl_xor_sync(0xffffffffu, p0, off);
            p1 += __shfl_xor_sync(0xffffffffu, p1, off);
        }
        float ex0 = __expf(p0 * pr0);
        float ex1 = __expf(p1 * pr1);
        ssum0 += ex0; ssum1 += ex1;
        const float4* vr = (const float4*)(V + (size_t)sn * DIM);
        float4 v0 = vr[lane], v1 = vr[lane + 32];
        a0.x += ex0 * v0.x; a0.y += ex0 * v0.y; a0.z += ex0 * v0.z; a0.w += ex0 * v0.w;
        a1.x += ex1 * v1.x; a1.y += ex1 * v1.y; a1.z += ex1 * v1.z; a1.w += ex1 * v1.w;
    }
    float i0 = (ssum0 > 0.f) ? 1.f / ssum0 : 0.f;
    float i1 = (ssum1 > 0.f) ? 1.f / ssum1 : 0.f;
    float4* ar = (float4*)(ep.agg[r] + (size_t)n * DIM);
    float4 o0; o0.x = a0.x * i0; o0.y = a0.y * i0; o0.z = a0.z * i0; o0.w = a0.w * i0;
    float4 o1; o1.x = a1.x * i1; o1.y = a1.y * i1; o1.z = a1.z * i1; o1.w = a1.w * i1;
    ar[lane]      = o0;
    ar[lane + 32] = o1;
}

// ---------------- combine: cross-relation mean + tf32 round + k-permute ----------------
__global__ void combine_kernel() {
    int j = blockIdx.x * blockDim.x + threadIdx.x;
    if (j >= NODE_F / 8) return;
    float4 a1l = ((const float4*)g_agg[1])[2 * j];
    float4 a1h = ((const float4*)g_agg[1])[2 * j + 1];
    float4 a2l = ((const float4*)g_agg[2])[2 * j];
    float4 a2h = ((const float4*)g_agg[2])[2 * j + 1];
    float c0 = 0.5f * (a1l.x + a2l.x), c1 = 0.5f * (a1l.y + a2l.y);
    float c2 = 0.5f * (a1l.z + a2l.z), c3 = 0.5f * (a1l.w + a2l.w);
    float c4 = 0.5f * (a1h.x + a2h.x), c5 = 0.5f * (a1h.y + a2h.y);
    float c6 = 0.5f * (a1h.z + a2h.z), c7 = 0.5f * (a1h.w + a2h.w);
    uint4 o0, o1;   // permuted order: 0,4,1,5 | 2,6,3,7
    o0.x = tf32r(c0); o0.y = tf32r(c4); o0.z = tf32r(c1); o0.w = tf32r(c5);
    o1.x = tf32r(c2); o1.y = tf32r(c6); o1.z = tf32r(c3); o1.w = tf32r(c7);
    ((uint4*)g_tt[0])[2 * j]     = o0;
    ((uint4*)g_tt[0])[2 * j + 1] = o1;

    float4 a0l = ((const float4*)g_agg[0])[2 * j];
    float4 a0h = ((const float4*)g_agg[0])[2 * j + 1];
    o0.x = tf32r(a0l.x); o0.y = tf32r(a0h.x); o0.z = tf32r(a0l.y); o0.w = tf32r(a0h.y);
    o1.x = tf32r(a0l.z); o1.y = tf32r(a0h.z); o1.z = tf32r(a0l.w); o1.w = tf32r(a0h.w);
    ((uint4*)g_tt[1])[2 * j]     = o0;
    ((uint4*)g_tt[1])[2 * j + 1] = o1;
}

// ---------------- launch ----------------
extern "C" void kernel_launch(void* const* d_in, const int* in_sizes, int n_in,
                              void* d_out, int out_size) {
    const float* h_A     = (const float*)d_in[0];
    const float* h_B     = (const float*)d_in[1];
    const float* Wk      = (const float*)d_in[2];
    const float* bk      = (const float*)d_in[3];
    const float* Wq      = (const float*)d_in[4];
    const float* bq      = (const float*)d_in[5];
    const float* Wv      = (const float*)d_in[6];
    const float* bv      = (const float*)d_in[7];
    const float* Wa      = (const float*)d_in[8];
    const float* ba      = (const float*)d_in[9];
    const float* rel_att = (const float*)d_in[10];
    const float* rel_msg = (const float*)d_in[11];
    const float* rel_pri = (const float*)d_in[12];
    const float* skip    = (const float*)d_in[13];
    const int*   src[3]  = {(const int*)d_in[14], (const int*)d_in[16], (const int*)d_in[18]};
    const int*   dst[3]  = {(const int*)d_in[15], (const int*)d_in[17], (const int*)d_in[19]};
    const int E = in_sizes[14];
    float* out = (float*)d_out;

    float *pHr[2], *pQ0, *pQ1, *pk[3], *pv[3], *pagg[3], *ptt[2];
    float *pWT, *pbc, *pWaT;
    {
        float* base;
        cudaGetSymbolAddress((void**)&base, g_hr);  pHr[0] = base; pHr[1] = base + NODE_F + PAD_F;
        cudaGetSymbolAddress((void**)&base, g_Q);   pQ0 = base; pQ1 = base + NODE_F;
        cudaGetSymbolAddress((void**)&base, g_k);   for (int r = 0; r < 3; r++) pk[r] = base + (size_t)r * NODE_F;
        cudaGetSymbolAddress((void**)&base, g_v);   for (int r = 0; r < 3; r++) pv[r] = base + (size_t)r * NODE_F;
        cudaGetSymbolAddress((void**)&pWT,  g_WT);
        cudaGetSymbolAddress((void**)&pbc,  g_bc);
        cudaGetSymbolAddress((void**)&pWaT, g_WaT);
        cudaGetSymbolAddress((void**)&base, g_agg); for (int r = 0; r < 3; r++) pagg[r] = base + (size_t)r * NODE_F;
        cudaGetSymbolAddress((void**)&base, g_tt);  ptt[0] = base; ptt[1] = base + NODE_F + PAD_F;
    }

    cudaFuncSetAttribute(tgemm, cudaFuncAttributeMaxDynamicSharedMemorySize, TG_SMEM);

    init_kernel<<<(NSEG + 255) / 256, 256>>>();
    round_kernel<<<1024, 256>>>(h_A, h_B);
    {
        int tot = TOTW + TOTB + TOTWA;
        build_all<<<(tot + 255) / 256, 256>>>(Wq, bq, Wk, bk, Wv, bv, Wa, rel_att, rel_msg);
    }

    // CSR build (independent of GEMMs)
    hist_kernel<<<(3 * E + 255) / 256, 256>>>(dst[0], dst[1], dst[2], E);
    scan1<<<469, 256>>>();
    scan2<<<1, 32>>>();
    scan3<<<469, 256>>>();
    scatter_kernel<<<(3 * E + 255) / 256, 256>>>(src[0], dst[0], src[1], dst[1], src[2], dst[2], E);

    int mblocks = (N_NODES + 127) / 128;

    // A-side fused projection: [40000 x 1280] -> Q0 | k0 | v0 | k2 | v2
    {
        OutPtrs o; o.p[0] = pQ0; o.p[1] = pk[0]; o.p[2] = pv[0]; o.p[3] = pk[2]; o.p[4] = pv[2];
        dim3 grid(10, mblocks);
        tgemm<<<grid, 256, TG_SMEM>>>(pHr[0], pWT, pbc, o, N_NODES, 0, nullptr, nullptr);
    }
    // B-side fused projection: [40000 x 768] -> Q1 | k1 | v1
    {
        OutPtrs o; o.p[0] = pQ1; o.p[1] = pk[1]; o.p[2] = pv[1]; o.p[3] = nullptr; o.p[4] = nullptr;
        dim3 grid(6, mblocks);
        tgemm<<<grid, 256, TG_SMEM>>>(pHr[1], pWT + 1280 * 256, pbc + 1280, o, N_NODES, 0, nullptr, nullptr);
    }

    // warp-per-dst aggregation; Q of dst type: r0->B(1), r1->A(0), r2->A(0)
    {
        EdgePtrs ep;
        ep.Q[0] = pQ1; ep.Q[1] = pQ0; ep.Q[2] = pQ0;
        for (int r = 0; r < 3; r++) { ep.K[r] = pk[r]; ep.V[r] = pv[r]; ep.agg[r] = pagg[r]; }
        int nwarp_blocks = (NSEG * 32 + 255) / 256;
        agg_kernel<<<nwarp_blocks, 256>>>(ep, rel_pri);
    }

    combine_kernel<<<(NODE_F / 8 + 255) / 256, 256>>>();

    // output GEMMs with fused skip epilogue
    {
        dim3 grid(2, mblocks);
        OutPtrs o; o.p[0] = out; o.p[1] = o.p[2] = o.p[3] = o.p[4] = nullptr;
        tgemm<<<grid, 256, TG_SMEM>>>(ptt[0], pWaT, ba, o, N_NODES, 1, skip, h_A);
        OutPtrs o2; o2.p[0] = out + NODE_F; o2.p[1] = o2.p[2] = o2.p[3] = o2.p[4] = nullptr;
        tgemm<<<grid, 256, TG_SMEM>>>(ptt[1], pWaT + 65536, ba + 256, o2, N_NODES, 1, skip + 1, h_B);
    }
}

// round 9
// speedup vs baseline: 1.2854x; 1.2276x over previous
#include <cuda_runtime.h>
#include <cuda_fp16.h>
#include <math.h>

#define N_NODES 40000
#define E_EDGES 200000
#define DIM 256
#define NHEAD 8
#define NODE_F (N_NODES * DIM)
#define PAD_F (64 * DIM)
#define NSEG (3 * N_NODES)

// ---------------- scratch (device globals) ----------------
__device__ __half g_hrh[2][NODE_F + PAD_F];   // fp16, k-permuted copies of h_A, h_B
__device__ float  g_Q[2][NODE_F];
__device__ float  g_k[3][NODE_F];
__device__ float  g_v[3][NODE_F];
__device__ __half g_WTh[2048 * 256];          // K-major concat weights, fp16, k-permuted
__device__ float  g_bc[2048];
__device__ __half g_WaTh[2 * 256 * 256];      // Wa^T, fp16, k-permuted
__device__ float  g_agg[3][NODE_F];
__device__ __half g_tth[2][NODE_F + PAD_F];   // combined features, fp16, k-permuted
__device__ int    g_hist[NSEG];
__device__ int    g_rowptr[NSEG + 1];
__device__ int    g_cursor[NSEG];
__device__ int    g_bsum[512];
__device__ int    g_csr[3 * E_EDGES];

struct Job {
    const __half* A; const __half* W; const float* bias; float* outp;
    const float* Hres; const float* skipv; int cin; int mode;
};
struct Jobs { Job j[16]; };
struct EdgePtrs { const float* Q[3]; const float* K[3]; const float* V[3]; float* agg[3]; };

// ---------------- helpers ----------------
__device__ __forceinline__ unsigned pack2(float a, float b) {
    __half2 h = __floats2half2_rn(a, b);
    return *(unsigned*)&h;
}
__device__ __forceinline__ void mma_f16(float* d, const unsigned* a, const unsigned* b) {
    asm volatile(
        "mma.sync.aligned.m16n8k16.row.col.f32.f16.f16.f32 "
        "{%0,%1,%2,%3}, {%4,%5,%6,%7}, {%8,%9}, {%0,%1,%2,%3};"
        : "+f"(d[0]), "+f"(d[1]), "+f"(d[2]), "+f"(d[3])
        : "r"(a[0]), "r"(a[1]), "r"(a[2]), "r"(a[3]), "r"(b[0]), "r"(b[1]));
}
__device__ __forceinline__ void cpa16(unsigned saddr, const void* g) {
    asm volatile("cp.async.cg.shared.global [%0], [%1], 16;" :: "r"(saddr), "l"(g));
}
__device__ __forceinline__ unsigned smem_u32(const void* p) {
    unsigned a;
    asm("{ .reg .u64 t; cvta.to.shared.u64 t, %1; cvt.u32.u64 %0, t; }" : "=r"(a) : "l"(p));
    return a;
}

// ---------------- init: hist=0 ----------------
__global__ void init_kernel() {
    int i = blockIdx.x * blockDim.x + threadIdx.x;
    if (i < NSEG) g_hist[i] = 0;
}

// ---------------- round inputs -> fp16 with k-permutation ----------------
// per 16-value group: words W0..W7 (half2) emitted as [W0,W4,W1,W5],[W2,W6,W3,W7]
__global__ void round_kernel(const float* __restrict__ hA, const float* __restrict__ hB) {
    int stride = gridDim.x * blockDim.x;
    const int ngrp = NODE_F / 16;
    for (int i = blockIdx.x * blockDim.x + threadIdx.x; i < ngrp; i += stride) {
        #pragma unroll
        for (int t = 0; t < 2; t++) {
            const float* src = t ? hB : hA;
            float4 f0 = ((const float4*)src)[4 * i + 0];
            float4 f1 = ((const float4*)src)[4 * i + 1];
            float4 f2 = ((const float4*)src)[4 * i + 2];
            float4 f3 = ((const float4*)src)[4 * i + 3];
            unsigned W0 = pack2(f0.x, f0.y), W1 = pack2(f0.z, f0.w);
            unsigned W2 = pack2(f1.x, f1.y), W3 = pack2(f1.z, f1.w);
            unsigned W4 = pack2(f2.x, f2.y), W5 = pack2(f2.z, f2.w);
            unsigned W6 = pack2(f3.x, f3.y), W7 = pack2(f3.z, f3.w);
            uint4 o0 = make_uint4(W0, W4, W1, W5);
            uint4 o1 = make_uint4(W2, W6, W3, W7);
            ((uint4*)g_hrh[t])[2 * i]     = o0;
            ((uint4*)g_hrh[t])[2 * i + 1] = o1;
        }
    }
}

// ---------------- build weights (fp16, k-permuted) + biases ----------------
#define TOTW  (2048 * 256)
#define TOTB  2048
#define TOTWA (2 * 256 * 256)
__device__ __forceinline__ int halfidx(int k) {
    int w = k >> 1, h = k & 1, wi = w & 7;
    int pw = (wi < 4) ? 2 * wi : 2 * wi - 7;
    return ((w >> 3) << 4) + pw * 2 + h;
}
__global__ void build_all(const float* __restrict__ Wq, const float* __restrict__ bq,
                          const float* __restrict__ Wk, const float* __restrict__ bk,
                          const float* __restrict__ Wv, const float* __restrict__ bv,
                          const float* __restrict__ Wa,
                          const float* __restrict__ rel_att, const float* __restrict__ rel_msg) {
    int gid = blockIdx.x * blockDim.x + threadIdx.x;
    if (gid < TOTW) {
        int k = gid & 255;
        int n = gid >> 8;
        int side  = (n < 1280) ? 0 : 1;
        int local = side ? (n - 1280) : n;
        int g = local >> 8, col = local & 255;
        float val;
        if (g == 0) {
            val = Wq[side * 65536 + k * 256 + col];
        } else {
            int r   = side ? 1 : ((g <= 2) ? 0 : 2);
            int isv = side ? (g == 2) : ((g & 1) == 0);
            const float* W  = (isv ? Wv : Wk) + side * 65536 + k * 256 + (col >> 5) * 32;
            const float* rp = (isv ? rel_msg : rel_att) + r * 8192 + (col >> 5) * 1024 + (col & 31);
            float acc = 0.f;
            #pragma unroll
            for (int d = 0; d < 32; d++) acc += W[d] * rp[d * 32];
            val = acc;
        }
        g_WTh[n * 256 + halfidx(k)] = __float2half_rn(val);
    } else if (gid < TOTW + TOTB) {
        int n = gid - TOTW;
        int side  = (n < 1280) ? 0 : 1;
        int local = side ? (n - 1280) : n;
        int g = local >> 8, col = local & 255;
        float val;
        if (g == 0) {
            val = bq[side * 256 + col];
        } else {
            int r   = side ? 1 : ((g <= 2) ? 0 : 2);
            int isv = side ? (g == 2) : ((g & 1) == 0);
            const float* b  = (isv ? bv : bk) + side * 256 + (col >> 5) * 32;
            const float* rp = (isv ? rel_msg : rel_att) + r * 8192 + (col >> 5) * 1024 + (col & 31);
            float acc = 0.f;
            #pragma unroll
            for (int d = 0; d < 32; d++) acc += b[d] * rp[d * 32];
            val = acc;
        }
        g_bc[n] = val;
    } else if (gid < TOTW + TOTB + TOTWA) {
        int i = gid - TOTW - TOTB;
        int k = i & 255, nn = (i >> 8) & 255, t = i >> 16;
        g_WaTh[t * 65536 + nn * 256 + halfidx(k)] = __float2half_rn(Wa[t * 65536 + k * 256 + nn]);
    }
}

// ---------------- fp16 mma.sync GEMM, cp.async 2-stage, K-chunks of 64 halves ----------------
// CTA tile 128x128, warp tile 64x32 (2x4 warps), 4 chunks, smem row stride 40 b32 words
#define SSTR32 40
#define STG_WORDS 10240           // per stage: A(5120) + B(5120) b32 words
#define STG_BYTES 40960u
#define TG_SMEM 81920
__global__ void __launch_bounds__(256, 2) tgemm(Jobs jobs, int M) {
    extern __shared__ float smem[];
    unsigned sbase = smem_u32(smem);
    Job jb = jobs.j[blockIdx.x];
    int tid = threadIdx.x, lane = tid & 31, wid = tid >> 5;
    int row0 = blockIdx.y * 128;
    int wm = (wid >> 2) * 64;
    int wn = (wid & 3) * 32;
    int g = lane >> 2, c = lane & 3;

    float acc[4][4][4];
    #pragma unroll
    for (int i = 0; i < 4; i++)
        #pragma unroll
        for (int j = 0; j < 4; j++)
            #pragma unroll
            for (int q = 0; q < 4; q++) acc[i][j][q] = 0.f;

    // staging slots: 4 per operand; slot = i*256+tid -> row=slot>>3, jc=slot&7 (16B units)
    int r_st[4], jc_st[4];
    #pragma unroll
    for (int i = 0; i < 4; i++) {
        int sl = i * 256 + tid;
        r_st[i] = sl >> 3; jc_st[i] = sl & 7;
    }

    // prefetch chunk 0 -> stage 0
    #pragma unroll
    for (int i = 0; i < 4; i++) {
        unsigned so = sbase + (unsigned)(r_st[i] * 160 + jc_st[i] * 16);
        cpa16(so, jb.A + (size_t)(row0 + r_st[i]) * 256 + jc_st[i] * 8);
        cpa16(so + 20480u, jb.W + (size_t)r_st[i] * 256 + jc_st[i] * 8);
    }
    asm volatile("cp.async.commit_group;" ::: "memory");

    #pragma unroll
    for (int ck = 0; ck < 4; ck++) {
        asm volatile("cp.async.wait_group 0;" ::: "memory");
        __syncthreads();
        if (ck + 1 < 4) {
            unsigned stb = sbase + ((ck + 1) & 1) * STG_BYTES;
            #pragma unroll
            for (int i = 0; i < 4; i++) {
                unsigned so = stb + (unsigned)(r_st[i] * 160 + jc_st[i] * 16);
                cpa16(so, jb.A + (size_t)(row0 + r_st[i]) * 256 + (ck + 1) * 64 + jc_st[i] * 8);
                cpa16(so + 20480u, jb.W + (size_t)r_st[i] * 256 + (ck + 1) * 64 + jc_st[i] * 8);
            }
            asm volatile("cp.async.commit_group;" ::: "memory");
        }
        const unsigned* sAw = ((const unsigned*)smem) + (ck & 1) * STG_WORDS;
        const unsigned* sBw = sAw + 5120;
        #pragma unroll
        for (int s = 0; s < 4; s++) {
            unsigned af[4][4], bf[4][2];
            int kc = s * 8 + 2 * c;
            #pragma unroll
            for (int mt = 0; mt < 4; mt++) {
                int m = wm + mt * 16;
                uint2 lo = *(const uint2*)&sAw[(m + g)     * SSTR32 + kc];
                uint2 hi = *(const uint2*)&sAw[(m + g + 8) * SSTR32 + kc];
                af[mt][0] = lo.x; af[mt][1] = hi.x; af[mt][2] = lo.y; af[mt][3] = hi.y;
            }
            #pragma unroll
            for (int nt = 0; nt < 4; nt++) {
                uint2 b = *(const uint2*)&sBw[(wn + nt * 8 + g) * SSTR32 + kc];
                bf[nt][0] = b.x; bf[nt][1] = b.y;
            }
            #pragma unroll
            for (int mt = 0; mt < 4; mt++)
                #pragma unroll
                for (int nt = 0; nt < 4; nt++)
                    mma_f16(acc[mt][nt], af[mt], bf[nt]);
        }
    }

    // epilogue
    float alpha = 1.f, beta = 0.f;
    if (jb.mode == 1) {
        float sv = *jb.skipv;
        alpha = 1.f / (1.f + __expf(-sv));
        beta  = 1.f - alpha;
    }
    int cinb = jb.cin + wn;
    #pragma unroll
    for (int mt = 0; mt < 4; mt++) {
        #pragma unroll
        for (int half = 0; half < 2; half++) {
            int row = row0 + wm + mt * 16 + g + half * 8;
            if (row >= M) continue;
            #pragma unroll
            for (int nt = 0; nt < 4; nt++) {
                int lcol = wn + nt * 8 + 2 * c;
                int cin = cinb + nt * 8 + 2 * c;
                float v0 = acc[mt][nt][half * 2 + 0] + jb.bias[lcol];
                float v1 = acc[mt][nt][half * 2 + 1] + jb.bias[lcol + 1];
                if (jb.mode == 1) {
                    v0 = v0 * alpha + jb.Hres[(size_t)row * 256 + cin]     * beta;
                    v1 = v1 * alpha + jb.Hres[(size_t)row * 256 + cin + 1] * beta;
                }
                float2 o; o.x = v0; o.y = v1;
                *(float2*)(jb.outp + (size_t)row * 256 + cin) = o;
            }
        }
    }
}

// ---------------- CSR build ----------------
__global__ void hist_kernel(const int* __restrict__ d0, const int* __restrict__ d1,
                            const int* __restrict__ d2, int E) {
    int i = blockIdx.x * blockDim.x + threadIdx.x;
    if (i >= 3 * E) return;
    int r = i / E, e = i - r * E;
    const int* dd = (r == 0) ? d0 : ((r == 1) ? d1 : d2);
    atomicAdd(&g_hist[r * N_NODES + dd[e]], 1);
}
__global__ void scan1() {
    __shared__ int sh[256];
    int i = blockIdx.x * 256 + threadIdx.x;
    sh[threadIdx.x] = (i < NSEG) ? g_hist[i] : 0;
    __syncthreads();
    for (int o = 128; o > 0; o >>= 1) {
        if (threadIdx.x < o) sh[threadIdx.x] += sh[threadIdx.x + o];
        __syncthreads();
    }
    if (threadIdx.x == 0) g_bsum[blockIdx.x] = sh[0];
}
__global__ void scan2() {
    if (threadIdx.x == 0) {
        int a = 0;
        for (int b = 0; b < 469; b++) { int t = g_bsum[b]; g_bsum[b] = a; a += t; }
        g_rowptr[NSEG] = a;
    }
}
__global__ void scan3() {
    __shared__ int sh[256];
    int i = blockIdx.x * 256 + threadIdx.x;
    int v = (i < NSEG) ? g_hist[i] : 0;
    sh[threadIdx.x] = v;
    __syncthreads();
    for (int o = 1; o < 256; o <<= 1) {
        int t = (threadIdx.x >= (unsigned)o) ? sh[threadIdx.x - o] : 0;
        __syncthreads();
        sh[threadIdx.x] += t;
        __syncthreads();
    }
    int excl = sh[threadIdx.x] - v + g_bsum[blockIdx.x];
    if (i < NSEG) { g_rowptr[i] = excl; g_cursor[i] = excl; }
}
__global__ void scatter_kernel(const int* __restrict__ s0, const int* __restrict__ d0,
                               const int* __restrict__ s1, const int* __restrict__ d1,
                               const int* __restrict__ s2, const int* __restrict__ d2, int E) {
    int i = blockIdx.x * blockDim.x + threadIdx.x;
    if (i >= 3 * E) return;
    int r = i / E, e = i - r * E;
    const int* ss = (r == 0) ? s0 : ((r == 1) ? s1 : s2);
    const int* dd = (r == 0) ? d0 : ((r == 1) ? d1 : d2);
    int pos = atomicAdd(&g_cursor[r * N_NODES + dd[e]], 1);
    g_csr[pos] = ss[e];
}

// ---------------- edge aggregation: one warp per (relation, dst) ----------------
__global__ void agg_kernel(EdgePtrs ep, const float* __restrict__ rel_pri) {
    int gw = (blockIdx.x * blockDim.x + threadIdx.x) >> 5;
    int lane = threadIdx.x & 31;
    if (gw >= NSEG) return;
    int r = gw / N_NODES, n = gw - r * N_NODES;
    const float* Q = ep.Q[r];
    const float* K = ep.K[r];
    const float* V = ep.V[r];
    const float rs = 0.17677669529663687f;
    float pr0 = rel_pri[r * NHEAD + (lane >> 3)] * rs;
    float pr1 = rel_pri[r * NHEAD + (lane >> 3) + 4] * rs;
    int beg = g_rowptr[gw], end = g_rowptr[gw + 1];
    const float4* qr = (const float4*)(Q + (size_t)n * DIM);
    float4 q0 = qr[lane], q1 = qr[lane + 32];
    float4 a0 = make_float4(0.f, 0.f, 0.f, 0.f);
    float4 a1 = make_float4(0.f, 0.f, 0.f, 0.f);
    float ssum0 = 0.f, ssum1 = 0.f;
    for (int i = beg; i < end; i++) {
        int sn = g_csr[i];
        const float4* kr = (const float4*)(K + (size_t)sn * DIM);
        float4 k0 = kr[lane], k1 = kr[lane + 32];
        float p0 = q0.x * k0.x + q0.y * k0.y + q0.z * k0.z + q0.w * k0.w;
        float p1 = q1.x * k1.x + q1.y * k1.y + q1.z * k1.z + q1.w * k1.w;
        #pragma unroll
        for (int off = 4; off >= 1; off >>= 1) {
            p0 += __shfl_xor_sync(0xffffffffu, p0, off);
            p1 += __shfl_xor_sync(0xffffffffu, p1, off);
        }
        float ex0 = __expf(p0 * pr0);
        float ex1 = __expf(p1 * pr1);
        ssum0 += ex0; ssum1 += ex1;
        const float4* vr = (const float4*)(V + (size_t)sn * DIM);
        float4 v0 = vr[lane], v1 = vr[lane + 32];
        a0.x += ex0 * v0.x; a0.y += ex0 * v0.y; a0.z += ex0 * v0.z; a0.w += ex0 * v0.w;
        a1.x += ex1 * v1.x; a1.y += ex1 * v1.y; a1.z += ex1 * v1.z; a1.w += ex1 * v1.w;
    }
    float i0 = (ssum0 > 0.f) ? 1.f / ssum0 : 0.f;
    float i1 = (ssum1 > 0.f) ? 1.f / ssum1 : 0.f;
    float4* ar = (float4*)(ep.agg[r] + (size_t)n * DIM);
    float4 o0; o0.x = a0.x * i0; o0.y = a0.y * i0; o0.z = a0.z * i0; o0.w = a0.w * i0;
    float4 o1; o1.x = a1.x * i1; o1.y = a1.y * i1; o1.z = a1.z * i1; o1.w = a1.w * i1;
    ar[lane]      = o0;
    ar[lane + 32] = o1;
}

// ---------------- combine: cross-relation mean -> fp16 k-permuted g_tth ----------------
__global__ void combine_kernel() {
    int j = blockIdx.x * blockDim.x + threadIdx.x;     // 16-value group index
    if (j >= NODE_F / 16) return;
    // type A: mean of relations 1,2
    {
        float4 f[4];
        #pragma unroll
        for (int q = 0; q < 4; q++) {
            float4 a1 = ((const float4*)g_agg[1])[4 * j + q];
            float4 a2 = ((const float4*)g_agg[2])[4 * j + q];
            f[q].x = 0.5f * (a1.x + a2.x); f[q].y = 0.5f * (a1.y + a2.y);
            f[q].z = 0.5f * (a1.z + a2.z); f[q].w = 0.5f * (a1.w + a2.w);
        }
        unsigned W0 = pack2(f[0].x, f[0].y), W1 = pack2(f[0].z, f[0].w);
        unsigned W2 = pack2(f[1].x, f[1].y), W3 = pack2(f[1].z, f[1].w);
        unsigned W4 = pack2(f[2].x, f[2].y), W5 = pack2(f[2].z, f[2].w);
        unsigned W6 = pack2(f[3].x, f[3].y), W7 = pack2(f[3].z, f[3].w);
        ((uint4*)g_tth[0])[2 * j]     = make_uint4(W0, W4, W1, W5);
        ((uint4*)g_tth[0])[2 * j + 1] = make_uint4(W2, W6, W3, W7);
    }
    // type B: relation 0
    {
        float4 f[4];
        #pragma unroll
        for (int q = 0; q < 4; q++) f[q] = ((const float4*)g_agg[0])[4 * j + q];
        unsigned W0 = pack2(f[0].x, f[0].y), W1 = pack2(f[0].z, f[0].w);
        unsigned W2 = pack2(f[1].x, f[1].y), W3 = pack2(f[1].z, f[1].w);
        unsigned W4 = pack2(f[2].x, f[2].y), W5 = pack2(f[2].z, f[2].w);
        unsigned W6 = pack2(f[3].x, f[3].y), W7 = pack2(f[3].z, f[3].w);
        ((uint4*)g_tth[1])[2 * j]     = make_uint4(W0, W4, W1, W5);
        ((uint4*)g_tth[1])[2 * j + 1] = make_uint4(W2, W6, W3, W7);
    }
}

// ---------------- launch ----------------
extern "C" void kernel_launch(void* const* d_in, const int* in_sizes, int n_in,
                              void* d_out, int out_size) {
    const float* h_A     = (const float*)d_in[0];
    const float* h_B     = (const float*)d_in[1];
    const float* Wk      = (const float*)d_in[2];
    const float* bk      = (const float*)d_in[3];
    const float* Wq      = (const float*)d_in[4];
    const float* bq      = (const float*)d_in[5];
    const float* Wv      = (const float*)d_in[6];
    const float* bv      = (const float*)d_in[7];
    const float* Wa      = (const float*)d_in[8];
    const float* ba      = (const float*)d_in[9];
    const float* rel_att = (const float*)d_in[10];
    const float* rel_msg = (const float*)d_in[11];
    const float* rel_pri = (const float*)d_in[12];
    const float* skip    = (const float*)d_in[13];
    const int*   src[3]  = {(const int*)d_in[14], (const int*)d_in[16], (const int*)d_in[18]};
    const int*   dst[3]  = {(const int*)d_in[15], (const int*)d_in[17], (const int*)d_in[19]};
    const int E = in_sizes[14];
    float* out = (float*)d_out;

    __half *pHr[2], *pWTh, *pWaTh, *ptt[2];
    float *pQ0, *pQ1, *pk[3], *pv[3], *pagg[3], *pbc;
    {
        void* base;
        cudaGetSymbolAddress(&base, g_hrh);  pHr[0] = (__half*)base; pHr[1] = (__half*)base + NODE_F + PAD_F;
        cudaGetSymbolAddress(&base, g_Q);    pQ0 = (float*)base; pQ1 = (float*)base + NODE_F;
        cudaGetSymbolAddress(&base, g_k);    for (int r = 0; r < 3; r++) pk[r] = (float*)base + (size_t)r * NODE_F;
        cudaGetSymbolAddress(&base, g_v);    for (int r = 0; r < 3; r++) pv[r] = (float*)base + (size_t)r * NODE_F;
        cudaGetSymbolAddress(&base, g_WTh);  pWTh = (__half*)base;
        cudaGetSymbolAddress(&base, g_bc);   pbc = (float*)base;
        cudaGetSymbolAddress(&base, g_WaTh); pWaTh = (__half*)base;
        cudaGetSymbolAddress(&base, g_agg);  for (int r = 0; r < 3; r++) pagg[r] = (float*)base + (size_t)r * NODE_F;
        cudaGetSymbolAddress(&base, g_tth);  ptt[0] = (__half*)base; ptt[1] = (__half*)base + NODE_F + PAD_F;
    }

    cudaFuncSetAttribute(tgemm, cudaFuncAttributeMaxDynamicSharedMemorySize, TG_SMEM);

    init_kernel<<<(NSEG + 255) / 256, 256>>>();
    round_kernel<<<1024, 256>>>(h_A, h_B);
    {
        int tot = TOTW + TOTB + TOTWA;
        build_all<<<(tot + 255) / 256, 256>>>(Wq, bq, Wk, bk, Wv, bv, Wa, rel_att, rel_msg);
    }

    // CSR build
    hist_kernel<<<(3 * E + 255) / 256, 256>>>(dst[0], dst[1], dst[2], E);
    scan1<<<469, 256>>>();
    scan2<<<1, 32>>>();
    scan3<<<469, 256>>>();
    scatter_kernel<<<(3 * E + 255) / 256, 256>>>(src[0], dst[0], src[1], dst[1], src[2], dst[2], E);

    int mblocks = (N_NODES + 127) / 128;

    // merged projection GEMMs: 16 column-tiles (A-side 10, B-side 6)
    {
        Jobs jobs;
        float* targA[5] = {pQ0, pk[0], pv[0], pk[2], pv[2]};
        float* targB[3] = {pQ1, pk[1], pv[1]};
        for (int x = 0; x < 10; x++) {
            int col0 = x * 128;
            jobs.j[x] = { pHr[0], pWTh + (size_t)col0 * 256, pbc + col0,
                          targA[x >> 1], nullptr, nullptr, (x & 1) * 128, 0 };
        }
        for (int x2 = 0; x2 < 6; x2++) {
            int col0 = 1280 + x2 * 128;
            jobs.j[10 + x2] = { pHr[1], pWTh + (size_t)col0 * 256, pbc + col0,
                                targB[x2 >> 1], nullptr, nullptr, (x2 & 1) * 128, 0 };
        }
        dim3 grid(16, mblocks);
        tgemm<<<grid, 256, TG_SMEM>>>(jobs, N_NODES);
    }

    // warp-per-dst aggregation; Q of dst type: r0->B(1), r1->A(0), r2->A(0)
    {
        EdgePtrs ep;
        ep.Q[0] = pQ1; ep.Q[1] = pQ0; ep.Q[2] = pQ0;
        for (int r = 0; r < 3; r++) { ep.K[r] = pk[r]; ep.V[r] = pv[r]; ep.agg[r] = pagg[r]; }
        int nwarp_blocks = (NSEG * 32 + 255) / 256;
        agg_kernel<<<nwarp_blocks, 256>>>(ep, rel_pri);
    }

    combine_kernel<<<(NODE_F / 16 + 255) / 256, 256>>>();

    // merged output GEMMs with fused skip epilogue
    {
        Jobs jobs;
        for (int x = 0; x < 2; x++)
            jobs.j[x] = { ptt[0], pWaTh + (size_t)x * 128 * 256, ba + x * 128,
                          out, h_A, skip, x * 128, 1 };
        for (int x = 0; x < 2; x++)
            jobs.j[2 + x] = { ptt[1], pWaTh + 65536 + (size_t)x * 128 * 256, ba + 256 + x * 128,
                              out + NODE_F, h_B, skip + 1, x * 128, 1 };
        dim3 grid(4, mblocks);
        tgemm<<<grid, 256, TG_SMEM>>>(jobs, N_NODES);
    }
}

// round 10
// speedup vs baseline: 1.4966x; 1.1643x over previous
#include <cuda_runtime.h>
#include <cuda_fp16.h>
#include <math.h>

#define N_NODES 40000
#define E_EDGES 200000
#define DIM 256
#define NHEAD 8
#define NODE_F (N_NODES * DIM)
#define PAD_F (64 * DIM)
#define NSEG (3 * N_NODES)

// ---------------- scratch (device globals) ----------------
__device__ __half g_hrh[2][NODE_F + PAD_F];   // fp16, k-permuted copies of h_A, h_B
__device__ __half g_Qh[2][NODE_F];            // fp16 Q per node type
__device__ __half g_kh[3][NODE_F];            // fp16 relation k
__device__ __half g_vh[3][NODE_F];            // fp16 relation v
__device__ __half g_WTh[2048 * 256];          // K-major concat weights, fp16, k-permuted
__device__ float  g_bc[2048];
__device__ __half g_WaTh[2 * 256 * 256];      // Wa^T, fp16, k-permuted
__device__ __half g_tth[2][NODE_F + PAD_F];   // combined features, fp16, k-permuted
__device__ int    g_hist[NSEG];
__device__ int    g_rowptr[NSEG + 1];
__device__ int    g_cursor[NSEG];
__device__ int    g_bsum[512];
__device__ int    g_csr[3 * E_EDGES];

struct Job {
    const __half* A; const __half* W; const float* bias; void* outp;
    const float* Hres; const float* skipv; int cin; int mode;   // mode 0: half out, 1: f32 skip-mix
};
struct Jobs { Job j[16]; };

// ---------------- helpers ----------------
__device__ __forceinline__ unsigned pack2(float a, float b) {
    __half2 h = __floats2half2_rn(a, b);
    return *(unsigned*)&h;
}
__device__ __forceinline__ void mma_f16(float* d, const unsigned* a, const unsigned* b) {
    asm volatile(
        "mma.sync.aligned.m16n8k16.row.col.f32.f16.f16.f32 "
        "{%0,%1,%2,%3}, {%4,%5,%6,%7}, {%8,%9}, {%0,%1,%2,%3};"
        : "+f"(d[0]), "+f"(d[1]), "+f"(d[2]), "+f"(d[3])
        : "r"(a[0]), "r"(a[1]), "r"(a[2]), "r"(a[3]), "r"(b[0]), "r"(b[1]));
}
__device__ __forceinline__ void cpa16(unsigned saddr, const void* g) {
    asm volatile("cp.async.cg.shared.global [%0], [%1], 16;" :: "r"(saddr), "l"(g));
}
__device__ __forceinline__ unsigned smem_u32(const void* p) {
    unsigned a;
    asm("{ .reg .u64 t; cvta.to.shared.u64 t, %1; cvt.u32.u64 %0, t; }" : "=r"(a) : "l"(p));
    return a;
}
__device__ __forceinline__ void ld8h(const __half* p, float* f) {
    uint4 u = *(const uint4*)p;
    float2 a;
    a = __half22float2(*(__half2*)&u.x); f[0] = a.x; f[1] = a.y;
    a = __half22float2(*(__half2*)&u.y); f[2] = a.x; f[3] = a.y;
    a = __half22float2(*(__half2*)&u.z); f[4] = a.x; f[5] = a.y;
    a = __half22float2(*(__half2*)&u.w); f[6] = a.x; f[7] = a.y;
}

// ---------------- init: hist=0 ----------------
__global__ void init_kernel() {
    int i = blockIdx.x * blockDim.x + threadIdx.x;
    if (i < NSEG) g_hist[i] = 0;
}

// ---------------- round inputs -> fp16 with k-permutation ----------------
__global__ void round_kernel(const float* __restrict__ hA, const float* __restrict__ hB) {
    int stride = gridDim.x * blockDim.x;
    const int ngrp = NODE_F / 16;
    for (int i = blockIdx.x * blockDim.x + threadIdx.x; i < ngrp; i += stride) {
        #pragma unroll
        for (int t = 0; t < 2; t++) {
            const float* src = t ? hB : hA;
            float4 f0 = ((const float4*)src)[4 * i + 0];
            float4 f1 = ((const float4*)src)[4 * i + 1];
            float4 f2 = ((const float4*)src)[4 * i + 2];
            float4 f3 = ((const float4*)src)[4 * i + 3];
            unsigned W0 = pack2(f0.x, f0.y), W1 = pack2(f0.z, f0.w);
            unsigned W2 = pack2(f1.x, f1.y), W3 = pack2(f1.z, f1.w);
            unsigned W4 = pack2(f2.x, f2.y), W5 = pack2(f2.z, f2.w);
            unsigned W6 = pack2(f3.x, f3.y), W7 = pack2(f3.z, f3.w);
            ((uint4*)g_hrh[t])[2 * i]     = make_uint4(W0, W4, W1, W5);
            ((uint4*)g_hrh[t])[2 * i + 1] = make_uint4(W2, W6, W3, W7);
        }
    }
}

// ---------------- build weights (fp16, k-permuted) + biases ----------------
#define TOTW  (2048 * 256)
#define TOTB  2048
#define TOTWA (2 * 256 * 256)
__device__ __forceinline__ int halfidx(int k) {
    int w = k >> 1, h = k & 1, wi = w & 7;
    int pw = (wi < 4) ? 2 * wi : 2 * wi - 7;
    return ((w >> 3) << 4) + pw * 2 + h;
}
__global__ void build_all(const float* __restrict__ Wq, const float* __restrict__ bq,
                          const float* __restrict__ Wk, const float* __restrict__ bk,
                          const float* __restrict__ Wv, const float* __restrict__ bv,
                          const float* __restrict__ Wa,
                          const float* __restrict__ rel_att, const float* __restrict__ rel_msg) {
    int gid = blockIdx.x * blockDim.x + threadIdx.x;
    if (gid < TOTW) {
        int k = gid & 255;
        int n = gid >> 8;
        int side  = (n < 1280) ? 0 : 1;
        int local = side ? (n - 1280) : n;
        int g = local >> 8, col = local & 255;
        float val;
        if (g == 0) {
            val = Wq[side * 65536 + k * 256 + col];
        } else {
            int r   = side ? 1 : ((g <= 2) ? 0 : 2);
            int isv = side ? (g == 2) : ((g & 1) == 0);
            const float* W  = (isv ? Wv : Wk) + side * 65536 + k * 256 + (col >> 5) * 32;
            const float* rp = (isv ? rel_msg : rel_att) + r * 8192 + (col >> 5) * 1024 + (col & 31);
            float acc = 0.f;
            #pragma unroll
            for (int d = 0; d < 32; d++) acc += W[d] * rp[d * 32];
            val = acc;
        }
        g_WTh[n * 256 + halfidx(k)] = __float2half_rn(val);
    } else if (gid < TOTW + TOTB) {
        int n = gid - TOTW;
        int side  = (n < 1280) ? 0 : 1;
        int local = side ? (n - 1280) : n;
        int g = local >> 8, col = local & 255;
        float val;
        if (g == 0) {
            val = bq[side * 256 + col];
        } else {
            int r   = side ? 1 : ((g <= 2) ? 0 : 2);
            int isv = side ? (g == 2) : ((g & 1) == 0);
            const float* b  = (isv ? bv : bk) + side * 256 + (col >> 5) * 32;
            const float* rp = (isv ? rel_msg : rel_att) + r * 8192 + (col >> 5) * 1024 + (col & 31);
            float acc = 0.f;
            #pragma unroll
            for (int d = 0; d < 32; d++) acc += b[d] * rp[d * 32];
            val = acc;
        }
        g_bc[n] = val;
    } else if (gid < TOTW + TOTB + TOTWA) {
        int i = gid - TOTW - TOTB;
        int k = i & 255, nn = (i >> 8) & 255, t = i >> 16;
        g_WaTh[t * 65536 + nn * 256 + halfidx(k)] = __float2half_rn(Wa[t * 65536 + k * 256 + nn]);
    }
}

// ---------------- fp16 mma.sync GEMM, cp.async 2-stage, K-chunks of 64 halves ----------------
#define SSTR32 40
#define STG_WORDS 10240
#define STG_BYTES 40960u
#define TG_SMEM 81920
__global__ void __launch_bounds__(256, 2) tgemm(Jobs jobs, int M) {
    extern __shared__ float smem[];
    unsigned sbase = smem_u32(smem);
    Job jb = jobs.j[blockIdx.x];
    int tid = threadIdx.x, lane = tid & 31, wid = tid >> 5;
    int row0 = blockIdx.y * 128;
    int wm = (wid >> 2) * 64;
    int wn = (wid & 3) * 32;
    int g = lane >> 2, c = lane & 3;

    float acc[4][4][4];
    #pragma unroll
    for (int i = 0; i < 4; i++)
        #pragma unroll
        for (int j = 0; j < 4; j++)
            #pragma unroll
            for (int q = 0; q < 4; q++) acc[i][j][q] = 0.f;

    int r_st[4], jc_st[4];
    #pragma unroll
    for (int i = 0; i < 4; i++) {
        int sl = i * 256 + tid;
        r_st[i] = sl >> 3; jc_st[i] = sl & 7;
    }

    #pragma unroll
    for (int i = 0; i < 4; i++) {
        unsigned so = sbase + (unsigned)(r_st[i] * 160 + jc_st[i] * 16);
        cpa16(so, jb.A + (size_t)(row0 + r_st[i]) * 256 + jc_st[i] * 8);
        cpa16(so + 20480u, jb.W + (size_t)r_st[i] * 256 + jc_st[i] * 8);
    }
    asm volatile("cp.async.commit_group;" ::: "memory");

    #pragma unroll
    for (int ck = 0; ck < 4; ck++) {
        asm volatile("cp.async.wait_group 0;" ::: "memory");
        __syncthreads();
        if (ck + 1 < 4) {
            unsigned stb = sbase + ((ck + 1) & 1) * STG_BYTES;
            #pragma unroll
            for (int i = 0; i < 4; i++) {
                unsigned so = stb + (unsigned)(r_st[i] * 160 + jc_st[i] * 16);
                cpa16(so, jb.A + (size_t)(row0 + r_st[i]) * 256 + (ck + 1) * 64 + jc_st[i] * 8);
                cpa16(so + 20480u, jb.W + (size_t)r_st[i] * 256 + (ck + 1) * 64 + jc_st[i] * 8);
            }
            asm volatile("cp.async.commit_group;" ::: "memory");
        }
        const unsigned* sAw = ((const unsigned*)smem) + (ck & 1) * STG_WORDS;
        const unsigned* sBw = sAw + 5120;
        #pragma unroll
        for (int s = 0; s < 4; s++) {
            unsigned af[4][4], bf[4][2];
            int kc = s * 8 + 2 * c;
            #pragma unroll
            for (int mt = 0; mt < 4; mt++) {
                int m = wm + mt * 16;
                uint2 lo = *(const uint2*)&sAw[(m + g)     * SSTR32 + kc];
                uint2 hi = *(const uint2*)&sAw[(m + g + 8) * SSTR32 + kc];
                af[mt][0] = lo.x; af[mt][1] = hi.x; af[mt][2] = lo.y; af[mt][3] = hi.y;
            }
            #pragma unroll
            for (int nt = 0; nt < 4; nt++) {
                uint2 b = *(const uint2*)&sBw[(wn + nt * 8 + g) * SSTR32 + kc];
                bf[nt][0] = b.x; bf[nt][1] = b.y;
            }
            #pragma unroll
            for (int mt = 0; mt < 4; mt++)
                #pragma unroll
                for (int nt = 0; nt < 4; nt++)
                    mma_f16(acc[mt][nt], af[mt], bf[nt]);
        }
    }

    // epilogue
    float alpha = 1.f, beta = 0.f;
    if (jb.mode == 1) {
        float sv = *jb.skipv;
        alpha = 1.f / (1.f + __expf(-sv));
        beta  = 1.f - alpha;
    }
    int cinb = jb.cin + wn;
    #pragma unroll
    for (int mt = 0; mt < 4; mt++) {
        #pragma unroll
        for (int half = 0; half < 2; half++) {
            int row = row0 + wm + mt * 16 + g + half * 8;
            if (row >= M) continue;
            #pragma unroll
            for (int nt = 0; nt < 4; nt++) {
                int lcol = wn + nt * 8 + 2 * c;
                int cin = cinb + nt * 8 + 2 * c;
                float v0 = acc[mt][nt][half * 2 + 0] + jb.bias[lcol];
                float v1 = acc[mt][nt][half * 2 + 1] + jb.bias[lcol + 1];
                if (jb.mode == 1) {
                    float* O = (float*)jb.outp;
                    v0 = v0 * alpha + jb.Hres[(size_t)row * 256 + cin]     * beta;
                    v1 = v1 * alpha + jb.Hres[(size_t)row * 256 + cin + 1] * beta;
                    float2 o; o.x = v0; o.y = v1;
                    *(float2*)(O + (size_t)row * 256 + cin) = o;
                } else {
                    __half* H = (__half*)jb.outp;
                    *(unsigned*)(H + (size_t)row * 256 + cin) = pack2(v0, v1);
                }
            }
        }
    }
}

// ---------------- CSR build ----------------
__global__ void hist_kernel(const int* __restrict__ d0, const int* __restrict__ d1,
                            const int* __restrict__ d2, int E) {
    int i = blockIdx.x * blockDim.x + threadIdx.x;
    if (i >= 3 * E) return;
    int r = i / E, e = i - r * E;
    const int* dd = (r == 0) ? d0 : ((r == 1) ? d1 : d2);
    atomicAdd(&g_hist[r * N_NODES + dd[e]], 1);
}
__global__ void scan1() {
    __shared__ int sh[256];
    int i = blockIdx.x * 256 + threadIdx.x;
    sh[threadIdx.x] = (i < NSEG) ? g_hist[i] : 0;
    __syncthreads();
    for (int o = 128; o > 0; o >>= 1) {
        if (threadIdx.x < o) sh[threadIdx.x] += sh[threadIdx.x + o];
        __syncthreads();
    }
    if (threadIdx.x == 0) g_bsum[blockIdx.x] = sh[0];
}
__global__ void scan2() {
    if (threadIdx.x == 0) {
        int a = 0;
        for (int b = 0; b < 469; b++) { int t = g_bsum[b]; g_bsum[b] = a; a += t; }
        g_rowptr[NSEG] = a;
    }
}
__global__ void scan3() {
    __shared__ int sh[256];
    int i = blockIdx.x * 256 + threadIdx.x;
    int v = (i < NSEG) ? g_hist[i] : 0;
    sh[threadIdx.x] = v;
    __syncthreads();
    for (int o = 1; o < 256; o <<= 1) {
        int t = (threadIdx.x >= (unsigned)o) ? sh[threadIdx.x - o] : 0;
        __syncthreads();
        sh[threadIdx.x] += t;
        __syncthreads();
    }
    int excl = sh[threadIdx.x] - v + g_bsum[blockIdx.x];
    if (i < NSEG) { g_rowptr[i] = excl; g_cursor[i] = excl; }
}
__global__ void scatter_kernel(const int* __restrict__ s0, const int* __restrict__ d0,
                               const int* __restrict__ s1, const int* __restrict__ d1,
                               const int* __restrict__ s2, const int* __restrict__ d2, int E) {
    int i = blockIdx.x * blockDim.x + threadIdx.x;
    if (i >= 3 * E) return;
    int r = i / E, e = i - r * E;
    const int* ss = (r == 0) ? s0 : ((r == 1) ? s1 : s2);
    const int* dd = (r == 0) ? d0 : ((r == 1) ? d1 : d2);
    int pos = atomicAdd(&g_cursor[r * N_NODES + dd[e]], 1);
    g_csr[pos] = ss[e];
}

// ---------------- aggregation: one warp per (node-type, dst), writes g_tth directly ----------------
// lane l covers elements [8l, 8l+8) -> head l>>2; after xor-2/xor-1 reduce, every lane
// holds its own head's score. Per-relation softmax normalization in registers.
__global__ void agg_kernel(const float* __restrict__ rel_pri) {
    int gw = (blockIdx.x * blockDim.x + threadIdx.x) >> 5;
    int lane = threadIdx.x & 31;
    if (gw >= 2 * N_NODES) return;
    int t = (gw >= N_NODES) ? 1 : 0;
    int n = gw - t * N_NODES;
    const float rs = 0.17677669529663687f;   // 1/sqrt(32)
    int head = lane >> 2;

    float q[8];
    ld8h(g_Qh[t] + (size_t)n * DIM + 8 * lane, q);

    float outv[8];
    #pragma unroll
    for (int j = 0; j < 8; j++) outv[j] = 0.f;

    int rfirst = t ? 0 : 1;
    int rcount = t ? 1 : 2;
    float scale = t ? 1.f : 0.5f;

    for (int ri = 0; ri < rcount; ri++) {
        int r = rfirst + ri;
        float pr = rel_pri[r * NHEAD + head] * rs;
        int seg = r * N_NODES + n;
        int beg = g_rowptr[seg], end = g_rowptr[seg + 1];
        float a[8];
        #pragma unroll
        for (int j = 0; j < 8; j++) a[j] = 0.f;
        float ssum = 0.f;
        for (int i = beg; i < end; i++) {
            int sn = g_csr[i];
            float kk[8];
            ld8h(g_kh[r] + (size_t)sn * DIM + 8 * lane, kk);
            float p = q[0]*kk[0] + q[1]*kk[1] + q[2]*kk[2] + q[3]*kk[3]
                    + q[4]*kk[4] + q[5]*kk[5] + q[6]*kk[6] + q[7]*kk[7];
            p += __shfl_xor_sync(0xffffffffu, p, 2);
            p += __shfl_xor_sync(0xffffffffu, p, 1);
            float ex = __expf(p * pr);
            ssum += ex;
            float vv[8];
            ld8h(g_vh[r] + (size_t)sn * DIM + 8 * lane, vv);
            #pragma unroll
            for (int j = 0; j < 8; j++) a[j] += ex * vv[j];
        }
        float inv = (ssum > 0.f) ? scale / ssum : 0.f;
        #pragma unroll
        for (int j = 0; j < 8; j++) outv[j] += a[j] * inv;
    }

    // write k-permuted fp16 row to g_tth[t]
    unsigned* orow = (unsigned*)(g_tth[t] + (size_t)n * DIM);
    #pragma unroll
    for (int j = 0; j < 4; j++) {
        int w = 4 * lane + j;
        int wi = w & 7;
        int pos = (w & ~7) + ((wi < 4) ? 2 * wi : 2 * wi - 7);
        orow[pos] = pack2(outv[2 * j], outv[2 * j + 1]);
    }
}

// ---------------- launch ----------------
extern "C" void kernel_launch(void* const* d_in, const int* in_sizes, int n_in,
                              void* d_out, int out_size) {
    const float* h_A     = (const float*)d_in[0];
    const float* h_B     = (const float*)d_in[1];
    const float* Wk      = (const float*)d_in[2];
    const float* bk      = (const float*)d_in[3];
    const float* Wq      = (const float*)d_in[4];
    const float* bq      = (const float*)d_in[5];
    const float* Wv      = (const float*)d_in[6];
    const float* bv      = (const float*)d_in[7];
    const float* Wa      = (const float*)d_in[8];
    const float* ba      = (const float*)d_in[9];
    const float* rel_att = (const float*)d_in[10];
    const float* rel_msg = (const float*)d_in[11];
    const float* rel_pri = (const float*)d_in[12];
    const float* skip    = (const float*)d_in[13];
    const int*   src[3]  = {(const int*)d_in[14], (const int*)d_in[16], (const int*)d_in[18]};
    const int*   dst[3]  = {(const int*)d_in[15], (const int*)d_in[17], (const int*)d_in[19]};
    const int E = in_sizes[14];
    float* out = (float*)d_out;

    __half *pHr[2], *pQh[2], *pkh[3], *pvh[3], *pWTh, *pWaTh, *ptt[2];
    float *pbc;
    {
        void* base;
        cudaGetSymbolAddress(&base, g_hrh);  pHr[0] = (__half*)base; pHr[1] = (__half*)base + NODE_F + PAD_F;
        cudaGetSymbolAddress(&base, g_Qh);   pQh[0] = (__half*)base; pQh[1] = (__half*)base + NODE_F;
        cudaGetSymbolAddress(&base, g_kh);   for (int r = 0; r < 3; r++) pkh[r] = (__half*)base + (size_t)r * NODE_F;
        cudaGetSymbolAddress(&base, g_vh);   for (int r = 0; r < 3; r++) pvh[r] = (__half*)base + (size_t)r * NODE_F;
        cudaGetSymbolAddress(&base, g_WTh);  pWTh = (__half*)base;
        cudaGetSymbolAddress(&base, g_bc);   pbc = (float*)base;
        cudaGetSymbolAddress(&base, g_WaTh); pWaTh = (__half*)base;
        cudaGetSymbolAddress(&base, g_tth);  ptt[0] = (__half*)base; ptt[1] = (__half*)base + NODE_F + PAD_F;
    }

    cudaFuncSetAttribute(tgemm, cudaFuncAttributeMaxDynamicSharedMemorySize, TG_SMEM);

    init_kernel<<<(NSEG + 255) / 256, 256>>>();
    round_kernel<<<1024, 256>>>(h_A, h_B);
    {
        int tot = TOTW + TOTB + TOTWA;
        build_all<<<(tot + 255) / 256, 256>>>(Wq, bq, Wk, bk, Wv, bv, Wa, rel_att, rel_msg);
    }

    // CSR build
    hist_kernel<<<(3 * E + 255) / 256, 256>>>(dst[0], dst[1], dst[2], E);
    scan1<<<469, 256>>>();
    scan2<<<1, 32>>>();
    scan3<<<469, 256>>>();
    scatter_kernel<<<(3 * E + 255) / 256, 256>>>(src[0], dst[0], src[1], dst[1], src[2], dst[2], E);

    int mblocks = (N_NODES + 127) / 128;

    // merged projection GEMMs: 16 column-tiles (A-side 10, B-side 6) -> fp16 outputs
    {
        Jobs jobs;
        __half* targA[5] = {pQh[0], pkh[0], pvh[0], pkh[2], pvh[2]};
        __half* targB[3] = {pQh[1], pkh[1], pvh[1]};
        for (int x = 0; x < 10; x++) {
            int col0 = x * 128;
            jobs.j[x] = { pHr[0], pWTh + (size_t)col0 * 256, pbc + col0,
                          (void*)targA[x >> 1], nullptr, nullptr, (x & 1) * 128, 0 };
        }
        for (int x2 = 0; x2 < 6; x2++) {
            int col0 = 1280 + x2 * 128;
            jobs.j[10 + x2] = { pHr[1], pWTh + (size_t)col0 * 256, pbc + col0,
                                (void*)targB[x2 >> 1], nullptr, nullptr, (x2 & 1) * 128, 0 };
        }
        dim3 grid(16, mblocks);
        tgemm<<<grid, 256, TG_SMEM>>>(jobs, N_NODES);
    }

    // warp-per-(type,dst) aggregation, writes g_tth directly (combine fused)
    {
        int nwarp_blocks = (2 * N_NODES * 32 + 255) / 256;
        agg_kernel<<<nwarp_blocks, 256>>>(rel_pri);
    }

    // merged output GEMMs with fused skip epilogue (f32 out)
    {
        Jobs jobs;
        for (int x = 0; x < 2; x++)
            jobs.j[x] = { ptt[0], pWaTh + (size_t)x * 128 * 256, ba + x * 128,
                          (void*)out, h_A, skip, x * 128, 1 };
        for (int x = 0; x < 2; x++)
            jobs.j[2 + x] = { ptt[1], pWaTh + 65536 + (size_t)x * 128 * 256, ba + 256 + x * 128,
                              (void*)(out + NODE_F), h_B, skip + 1, x * 128, 1 };
        dim3 grid(4, mblocks);
        tgemm<<<grid, 256, TG_SMEM>>>(jobs, N_NODES);
    }
}

// round 11
// speedup vs baseline: 1.5421x; 1.0304x over previous
#include <cuda_runtime.h>
#include <cuda_fp16.h>
#include <math.h>

#define N_NODES 40000
#define E_EDGES 200000
#define DIM 256
#define NHEAD 8
#define NODE_F (N_NODES * DIM)
#define PAD_F (64 * DIM)
#define NSEG (3 * N_NODES)

// ---------------- scratch (device globals) ----------------
__device__ __half g_hrh[2][NODE_F + PAD_F];   // fp16, k-permuted copies of h_A, h_B
__device__ __half g_Qh[2][NODE_F];
__device__ __half g_kh[3][NODE_F];
__device__ __half g_vh[3][NODE_F];
__device__ __half g_WTh[2048 * 256];
__device__ float  g_bc[2048];
__device__ __half g_WaTh[2 * 256 * 256];
__device__ __half g_tth[2][NODE_F + PAD_F];
__device__ int    g_hist[NSEG];               // zero at load; scan3 re-zeroes each run
__device__ int    g_rowptr[NSEG + 1];
__device__ int    g_cursor[NSEG];
__device__ int    g_bsum[512];
__device__ int    g_csr[3 * E_EDGES];

struct Job {
    const __half* A; const __half* W; const float* bias; void* outp;
    const float* Hres; const float* skipv; int cin; int mode;
};
struct Jobs { Job j[16]; };

// ---------------- helpers ----------------
__device__ __forceinline__ unsigned pack2(float a, float b) {
    __half2 h = __floats2half2_rn(a, b);
    return *(unsigned*)&h;
}
__device__ __forceinline__ void mma_f16(float* d, const unsigned* a, const unsigned* b) {
    asm volatile(
        "mma.sync.aligned.m16n8k16.row.col.f32.f16.f16.f32 "
        "{%0,%1,%2,%3}, {%4,%5,%6,%7}, {%8,%9}, {%0,%1,%2,%3};"
        : "+f"(d[0]), "+f"(d[1]), "+f"(d[2]), "+f"(d[3])
        : "r"(a[0]), "r"(a[1]), "r"(a[2]), "r"(a[3]), "r"(b[0]), "r"(b[1]));
}
__device__ __forceinline__ void cpa16(unsigned saddr, const void* g) {
    asm volatile("cp.async.cg.shared.global [%0], [%1], 16;" :: "r"(saddr), "l"(g));
}
__device__ __forceinline__ unsigned smem_u32(const void* p) {
    unsigned a;
    asm("{ .reg .u64 t; cvta.to.shared.u64 t, %1; cvt.u32.u64 %0, t; }" : "=r"(a) : "l"(p));
    return a;
}
__device__ __forceinline__ void ld8h(const __half* p, float* f) {
    uint4 u = *(const uint4*)p;
    float2 a;
    a = __half22float2(*(__half2*)&u.x); f[0] = a.x; f[1] = a.y;
    a = __half22float2(*(__half2*)&u.y); f[2] = a.x; f[3] = a.y;
    a = __half22float2(*(__half2*)&u.z); f[4] = a.x; f[5] = a.y;
    a = __half22float2(*(__half2*)&u.w); f[6] = a.x; f[7] = a.y;
}

// ---------------- prep: round inputs + build weights/biases (merged) ----------------
#define NGRP  (NODE_F / 16)
#define TOTW  (2048 * 256)
#define TOTB  2048
#define TOTWA (2 * 256 * 256)
#define PREP_TOT (NGRP + TOTW + TOTB + TOTWA)
__device__ __forceinline__ int halfidx(int k) {
    int w = k >> 1, h = k & 1, wi = w & 7;
    int pw = (wi < 4) ? 2 * wi : 2 * wi - 7;
    return ((w >> 3) << 4) + pw * 2 + h;
}
__global__ void prep_kernel(const float* __restrict__ hA, const float* __restrict__ hB,
                            const float* __restrict__ Wq, const float* __restrict__ bq,
                            const float* __restrict__ Wk, const float* __restrict__ bk,
                            const float* __restrict__ Wv, const float* __restrict__ bv,
                            const float* __restrict__ Wa,
                            const float* __restrict__ rel_att, const float* __restrict__ rel_msg) {
    int gid = blockIdx.x * blockDim.x + threadIdx.x;
    if (gid < NGRP) {
        int i = gid;
        #pragma unroll
        for (int t = 0; t < 2; t++) {
            const float* src = t ? hB : hA;
            float4 f0 = ((const float4*)src)[4 * i + 0];
            float4 f1 = ((const float4*)src)[4 * i + 1];
            float4 f2 = ((const float4*)src)[4 * i + 2];
            float4 f3 = ((const float4*)src)[4 * i + 3];
            unsigned W0 = pack2(f0.x, f0.y), W1 = pack2(f0.z, f0.w);
            unsigned W2 = pack2(f1.x, f1.y), W3 = pack2(f1.z, f1.w);
            unsigned W4 = pack2(f2.x, f2.y), W5 = pack2(f2.z, f2.w);
            unsigned W6 = pack2(f3.x, f3.y), W7 = pack2(f3.z, f3.w);
            ((uint4*)g_hrh[t])[2 * i]     = make_uint4(W0, W4, W1, W5);
            ((uint4*)g_hrh[t])[2 * i + 1] = make_uint4(W2, W6, W3, W7);
        }
        return;
    }
    gid -= NGRP;
    if (gid < TOTW) {
        int k = gid & 255;
        int n = gid >> 8;
        int side  = (n < 1280) ? 0 : 1;
        int local = side ? (n - 1280) : n;
        int g = local >> 8, col = local & 255;
        float val;
        if (g == 0) {
            val = Wq[side * 65536 + k * 256 + col];
        } else {
            int r   = side ? 1 : ((g <= 2) ? 0 : 2);
            int isv = side ? (g == 2) : ((g & 1) == 0);
            const float* W  = (isv ? Wv : Wk) + side * 65536 + k * 256 + (col >> 5) * 32;
            const float* rp = (isv ? rel_msg : rel_att) + r * 8192 + (col >> 5) * 1024 + (col & 31);
            float acc = 0.f;
            #pragma unroll
            for (int d = 0; d < 32; d++) acc += W[d] * rp[d * 32];
            val = acc;
        }
        g_WTh[n * 256 + halfidx(k)] = __float2half_rn(val);
    } else if (gid < TOTW + TOTB) {
        int n = gid - TOTW;
        int side  = (n < 1280) ? 0 : 1;
        int local = side ? (n - 1280) : n;
        int g = local >> 8, col = local & 255;
        float val;
        if (g == 0) {
            val = bq[side * 256 + col];
        } else {
            int r   = side ? 1 : ((g <= 2) ? 0 : 2);
            int isv = side ? (g == 2) : ((g & 1) == 0);
            const float* b  = (isv ? bv : bk) + side * 256 + (col >> 5) * 32;
            const float* rp = (isv ? rel_msg : rel_att) + r * 8192 + (col >> 5) * 1024 + (col & 31);
            float acc = 0.f;
            #pragma unroll
            for (int d = 0; d < 32; d++) acc += b[d] * rp[d * 32];
            val = acc;
        }
        g_bc[n] = val;
    } else if (gid < TOTW + TOTB + TOTWA) {
        int i = gid - TOTW - TOTB;
        int k = i & 255, nn = (i >> 8) & 255, t = i >> 16;
        g_WaTh[t * 65536 + nn * 256 + halfidx(k)] = __float2half_rn(Wa[t * 65536 + k * 256 + nn]);
    }
}

// ---------------- fp16 mma.sync GEMM, cp.async 2-stage, K-chunks of 64 halves ----------------
#define SSTR32 40
#define STG_WORDS 10240
#define STG_BYTES 40960u
#define TG_SMEM 81920
__global__ void __launch_bounds__(256, 2) tgemm(Jobs jobs, int M) {
    extern __shared__ float smem[];
    unsigned sbase = smem_u32(smem);
    Job jb = jobs.j[blockIdx.x];
    int tid = threadIdx.x, lane = tid & 31, wid = tid >> 5;
    int row0 = blockIdx.y * 128;
    int wm = (wid >> 2) * 64;
    int wn = (wid & 3) * 32;
    int g = lane >> 2, c = lane & 3;

    float acc[4][4][4];
    #pragma unroll
    for (int i = 0; i < 4; i++)
        #pragma unroll
        for (int j = 0; j < 4; j++)
            #pragma unroll
            for (int q = 0; q < 4; q++) acc[i][j][q] = 0.f;

    int r_st[4], jc_st[4];
    #pragma unroll
    for (int i = 0; i < 4; i++) {
        int sl = i * 256 + tid;
        r_st[i] = sl >> 3; jc_st[i] = sl & 7;
    }

    #pragma unroll
    for (int i = 0; i < 4; i++) {
        unsigned so = sbase + (unsigned)(r_st[i] * 160 + jc_st[i] * 16);
        cpa16(so, jb.A + (size_t)(row0 + r_st[i]) * 256 + jc_st[i] * 8);
        cpa16(so + 20480u, jb.W + (size_t)r_st[i] * 256 + jc_st[i] * 8);
    }
    asm volatile("cp.async.commit_group;" ::: "memory");

    #pragma unroll
    for (int ck = 0; ck < 4; ck++) {
        asm volatile("cp.async.wait_group 0;" ::: "memory");
        __syncthreads();
        if (ck + 1 < 4) {
            unsigned stb = sbase + ((ck + 1) & 1) * STG_BYTES;
            #pragma unroll
            for (int i = 0; i < 4; i++) {
                unsigned so = stb + (unsigned)(r_st[i] * 160 + jc_st[i] * 16);
                cpa16(so, jb.A + (size_t)(row0 + r_st[i]) * 256 + (ck + 1) * 64 + jc_st[i] * 8);
                cpa16(so + 20480u, jb.W + (size_t)r_st[i] * 256 + (ck + 1) * 64 + jc_st[i] * 8);
            }
            asm volatile("cp.async.commit_group;" ::: "memory");
        }
        const unsigned* sAw = ((const unsigned*)smem) + (ck & 1) * STG_WORDS;
        const unsigned* sBw = sAw + 5120;
        #pragma unroll
        for (int s = 0; s < 4; s++) {
            unsigned af[4][4], bf[4][2];
            int kc = s * 8 + 2 * c;
            #pragma unroll
            for (int mt = 0; mt < 4; mt++) {
                int m = wm + mt * 16;
                uint2 lo = *(const uint2*)&sAw[(m + g)     * SSTR32 + kc];
                uint2 hi = *(const uint2*)&sAw[(m + g + 8) * SSTR32 + kc];
                af[mt][0] = lo.x; af[mt][1] = hi.x; af[mt][2] = lo.y; af[mt][3] = hi.y;
            }
            #pragma unroll
            for (int nt = 0; nt < 4; nt++) {
                uint2 b = *(const uint2*)&sBw[(wn + nt * 8 + g) * SSTR32 + kc];
                bf[nt][0] = b.x; bf[nt][1] = b.y;
            }
            #pragma unroll
            for (int mt = 0; mt < 4; mt++)
                #pragma unroll
                for (int nt = 0; nt < 4; nt++)
                    mma_f16(acc[mt][nt], af[mt], bf[nt]);
        }
    }

    float alpha = 1.f, beta = 0.f;
    if (jb.mode == 1) {
        float sv = *jb.skipv;
        alpha = 1.f / (1.f + __expf(-sv));
        beta  = 1.f - alpha;
    }
    int cinb = jb.cin + wn;
    #pragma unroll
    for (int mt = 0; mt < 4; mt++) {
        #pragma unroll
        for (int half = 0; half < 2; half++) {
            int row = row0 + wm + mt * 16 + g + half * 8;
            if (row >= M) continue;
            #pragma unroll
            for (int nt = 0; nt < 4; nt++) {
                int lcol = wn + nt * 8 + 2 * c;
                int cin = cinb + nt * 8 + 2 * c;
                float v0 = acc[mt][nt][half * 2 + 0] + jb.bias[lcol];
                float v1 = acc[mt][nt][half * 2 + 1] + jb.bias[lcol + 1];
                if (jb.mode == 1) {
                    float* O = (float*)jb.outp;
                    v0 = v0 * alpha + jb.Hres[(size_t)row * 256 + cin]     * beta;
                    v1 = v1 * alpha + jb.Hres[(size_t)row * 256 + cin + 1] * beta;
                    float2 o; o.x = v0; o.y = v1;
                    *(float2*)(O + (size_t)row * 256 + cin) = o;
                } else {
                    __half* H = (__half*)jb.outp;
                    *(unsigned*)(H + (size_t)row * 256 + cin) = pack2(v0, v1);
                }
            }
        }
    }
}

// ---------------- CSR build ----------------
__global__ void hist_kernel(const int* __restrict__ d0, const int* __restrict__ d1,
                            const int* __restrict__ d2, int E) {
    int i = blockIdx.x * blockDim.x + threadIdx.x;
    if (i >= 3 * E) return;
    int r = i / E, e = i - r * E;
    const int* dd = (r == 0) ? d0 : ((r == 1) ? d1 : d2);
    atomicAdd(&g_hist[r * N_NODES + dd[e]], 1);
}
__global__ void scan1() {
    __shared__ int sh[256];
    int i = blockIdx.x * 256 + threadIdx.x;
    sh[threadIdx.x] = (i < NSEG) ? g_hist[i] : 0;
    __syncthreads();
    for (int o = 128; o > 0; o >>= 1) {
        if (threadIdx.x < o) sh[threadIdx.x] += sh[threadIdx.x + o];
        __syncthreads();
    }
    if (threadIdx.x == 0) g_bsum[blockIdx.x] = sh[0];
}
__global__ void scan2() {
    if (threadIdx.x == 0) {
        int a = 0;
        for (int b = 0; b < 469; b++) { int t = g_bsum[b]; g_bsum[b] = a; a += t; }
        g_rowptr[NSEG] = a;
    }
}
__global__ void scan3() {
    __shared__ int sh[256];
    int i = blockIdx.x * 256 + threadIdx.x;
    int v = (i < NSEG) ? g_hist[i] : 0;
    sh[threadIdx.x] = v;
    __syncthreads();
    for (int o = 1; o < 256; o <<= 1) {
        int t = (threadIdx.x >= (unsigned)o) ? sh[threadIdx.x - o] : 0;
        __syncthreads();
        sh[threadIdx.x] += t;
        __syncthreads();
    }
    int excl = sh[threadIdx.x] - v + g_bsum[blockIdx.x];
    if (i < NSEG) {
        g_rowptr[i] = excl;
        g_cursor[i] = excl;
        g_hist[i] = 0;                 // restore for next graph replay (zeroed at load)
    }
}
__global__ void scatter_kernel(const int* __restrict__ s0, const int* __restrict__ d0,
                               const int* __restrict__ s1, const int* __restrict__ d1,
                               const int* __restrict__ s2, const int* __restrict__ d2, int E) {
    int i = blockIdx.x * blockDim.x + threadIdx.x;
    if (i >= 3 * E) return;
    int r = i / E, e = i - r * E;
    const int* ss = (r == 0) ? s0 : ((r == 1) ? s1 : s2);
    const int* dd = (r == 0) ? d0 : ((r == 1) ? d1 : d2);
    int pos = atomicAdd(&g_cursor[r * N_NODES + dd[e]], 1);
    g_csr[pos] = ss[e];
}

// ---------------- aggregation: one warp per (node-type, dst), edge loop unrolled x2 ----------------
__global__ void agg_kernel(const float* __restrict__ rel_pri) {
    int gw = (blockIdx.x * blockDim.x + threadIdx.x) >> 5;
    int lane = threadIdx.x & 31;
    if (gw >= 2 * N_NODES) return;
    int t = (gw >= N_NODES) ? 1 : 0;
    int n = gw - t * N_NODES;
    const float rs = 0.17677669529663687f;
    int head = lane >> 2;

    float q[8];
    ld8h(g_Qh[t] + (size_t)n * DIM + 8 * lane, q);

    float outv[8];
    #pragma unroll
    for (int j = 0; j < 8; j++) outv[j] = 0.f;

    int rfirst = t ? 0 : 1;
    int rcount = t ? 1 : 2;
    float scale = t ? 1.f : 0.5f;

    for (int ri = 0; ri < rcount; ri++) {
        int r = rfirst + ri;
        float pr = rel_pri[r * NHEAD + head] * rs;
        int seg = r * N_NODES + n;
        int beg = g_rowptr[seg], end = g_rowptr[seg + 1];
        const __half* Kb = g_kh[r];
        const __half* Vb = g_vh[r];
        float a[8];
        #pragma unroll
        for (int j = 0; j < 8; j++) a[j] = 0.f;
        float ssum = 0.f;
        int i = beg;
        for (; i + 1 < end; i += 2) {
            int sn0 = g_csr[i], sn1 = g_csr[i + 1];
            float k0[8], k1[8], v0[8], v1[8];
            ld8h(Kb + (size_t)sn0 * DIM + 8 * lane, k0);
            ld8h(Kb + (size_t)sn1 * DIM + 8 * lane, k1);
            ld8h(Vb + (size_t)sn0 * DIM + 8 * lane, v0);
            ld8h(Vb + (size_t)sn1 * DIM + 8 * lane, v1);
            float p0 = q[0]*k0[0] + q[1]*k0[1] + q[2]*k0[2] + q[3]*k0[3]
                     + q[4]*k0[4] + q[5]*k0[5] + q[6]*k0[6] + q[7]*k0[7];
            float p1 = q[0]*k1[0] + q[1]*k1[1] + q[2]*k1[2] + q[3]*k1[3]
                     + q[4]*k1[4] + q[5]*k1[5] + q[6]*k1[6] + q[7]*k1[7];
            p0 += __shfl_xor_sync(0xffffffffu, p0, 2);
            p1 += __shfl_xor_sync(0xffffffffu, p1, 2);
            p0 += __shfl_xor_sync(0xffffffffu, p0, 1);
            p1 += __shfl_xor_sync(0xffffffffu, p1, 1);
            float ex0 = __expf(p0 * pr);
            float ex1 = __expf(p1 * pr);
            ssum += ex0 + ex1;
            #pragma unroll
            for (int j = 0; j < 8; j++) a[j] += ex0 * v0[j] + ex1 * v1[j];
        }
        if (i < end) {
            int sn = g_csr[i];
            float kk[8], vv[8];
            ld8h(Kb + (size_t)sn * DIM + 8 * lane, kk);
            ld8h(Vb + (size_t)sn * DIM + 8 * lane, vv);
            float p = q[0]*kk[0] + q[1]*kk[1] + q[2]*kk[2] + q[3]*kk[3]
                    + q[4]*kk[4] + q[5]*kk[5] + q[6]*kk[6] + q[7]*kk[7];
            p += __shfl_xor_sync(0xffffffffu, p, 2);
            p += __shfl_xor_sync(0xffffffffu, p, 1);
            float ex = __expf(p * pr);
            ssum += ex;
            #pragma unroll
            for (int j = 0; j < 8; j++) a[j] += ex * vv[j];
        }
        float inv = (ssum > 0.f) ? scale / ssum : 0.f;
        #pragma unroll
        for (int j = 0; j < 8; j++) outv[j] += a[j] * inv;
    }

    unsigned* orow = (unsigned*)(g_tth[t] + (size_t)n * DIM);
    #pragma unroll
    for (int j = 0; j < 4; j++) {
        int w = 4 * lane + j;
        int wi = w & 7;
        int pos = (w & ~7) + ((wi < 4) ? 2 * wi : 2 * wi - 7);
        orow[pos] = pack2(outv[2 * j], outv[2 * j + 1]);
    }
}

// ---------------- launch ----------------
extern "C" void kernel_launch(void* const* d_in, const int* in_sizes, int n_in,
                              void* d_out, int out_size) {
    const float* h_A     = (const float*)d_in[0];
    const float* h_B     = (const float*)d_in[1];
    const float* Wk      = (const float*)d_in[2];
    const float* bk      = (const float*)d_in[3];
    const float* Wq      = (const float*)d_in[4];
    const float* bq      = (const float*)d_in[5];
    const float* Wv      = (const float*)d_in[6];
    const float* bv      = (const float*)d_in[7];
    const float* Wa      = (const float*)d_in[8];
    const float* ba      = (const float*)d_in[9];
    const float* rel_att = (const float*)d_in[10];
    const float* rel_msg = (const float*)d_in[11];
    const float* rel_pri = (const float*)d_in[12];
    const float* skip    = (const float*)d_in[13];
    const int*   src[3]  = {(const int*)d_in[14], (const int*)d_in[16], (const int*)d_in[18]};
    const int*   dst[3]  = {(const int*)d_in[15], (const int*)d_in[17], (const int*)d_in[19]};
    const int E = in_sizes[14];
    float* out = (float*)d_out;

    __half *pHr[2], *pQh[2], *pkh[3], *pvh[3], *pWTh, *pWaTh, *ptt[2];
    float *pbc;
    {
        void* base;
        cudaGetSymbolAddress(&base, g_hrh);  pHr[0] = (__half*)base; pHr[1] = (__half*)base + NODE_F + PAD_F;
        cudaGetSymbolAddress(&base, g_Qh);   pQh[0] = (__half*)base; pQh[1] = (__half*)base + NODE_F;
        cudaGetSymbolAddress(&base, g_kh);   for (int r = 0; r < 3; r++) pkh[r] = (__half*)base + (size_t)r * NODE_F;
        cudaGetSymbolAddress(&base, g_vh);   for (int r = 0; r < 3; r++) pvh[r] = (__half*)base + (size_t)r * NODE_F;
        cudaGetSymbolAddress(&base, g_WTh);  pWTh = (__half*)base;
        cudaGetSymbolAddress(&base, g_bc);   pbc = (float*)base;
        cudaGetSymbolAddress(&base, g_WaTh); pWaTh = (__half*)base;
        cudaGetSymbolAddress(&base, g_tth);  ptt[0] = (__half*)base; ptt[1] = (__half*)base + NODE_F + PAD_F;
    }

    cudaFuncSetAttribute(tgemm, cudaFuncAttributeMaxDynamicSharedMemorySize, TG_SMEM);

    // prep (round + weight build, merged)
    prep_kernel<<<(PREP_TOT + 255) / 256, 256>>>(h_A, h_B, Wq, bq, Wk, bk, Wv, bv, Wa,
                                                 rel_att, rel_msg);

    // CSR build (g_hist is zeroed: at load by the runtime, per-run by scan3)
    hist_kernel<<<(3 * E + 255) / 256, 256>>>(dst[0], dst[1], dst[2], E);
    scan1<<<469, 256>>>();
    scan2<<<1, 32>>>();
    scan3<<<469, 256>>>();
    scatter_kernel<<<(3 * E + 255) / 256, 256>>>(src[0], dst[0], src[1], dst[1], src[2], dst[2], E);

    int mblocks = (N_NODES + 127) / 128;

    // merged projection GEMMs: 16 column-tiles -> fp16 outputs
    {
        Jobs jobs;
        __half* targA[5] = {pQh[0], pkh[0], pvh[0], pkh[2], pvh[2]};
        __half* targB[3] = {pQh[1], pkh[1], pvh[1]};
        for (int x = 0; x < 10; x++) {
            int col0 = x * 128;
            jobs.j[x] = { pHr[0], pWTh + (size_t)col0 * 256, pbc + col0,
                          (void*)targA[x >> 1], nullptr, nullptr, (x & 1) * 128, 0 };
        }
        for (int x2 = 0; x2 < 6; x2++) {
            int col0 = 1280 + x2 * 128;
            jobs.j[10 + x2] = { pHr[1], pWTh + (size_t)col0 * 256, pbc + col0,
                                (void*)targB[x2 >> 1], nullptr, nullptr, (x2 & 1) * 128, 0 };
        }
        dim3 grid(16, mblocks);
        tgemm<<<grid, 256, TG_SMEM>>>(jobs, N_NODES);
    }

    // warp-per-(type,dst) aggregation, writes g_tth directly
    {
        int nwarp_blocks = (2 * N_NODES * 32 + 255) / 256;
        agg_kernel<<<nwarp_blocks, 256>>>(rel_pri);
    }

    // merged output GEMMs with fused skip epilogue (f32 out)
    {
        Jobs jobs;
        for (int x = 0; x < 2; x++)
            jobs.j[x] = { ptt[0], pWaTh + (size_t)x * 128 * 256, ba + x * 128,
                          (void*)out, h_A, skip, x * 128, 1 };
        for (int x = 0; x < 2; x++)
            jobs.j[2 + x] = { ptt[1], pWaTh + 65536 + (size_t)x * 128 * 256, ba + 256 + x * 128,
                              (void*)(out + NODE_F), h_B, skip + 1, x * 128, 1 };
        dim3 grid(4, mblocks);
        tgemm<<<grid, 256, TG_SMEM>>>(jobs, N_NODES);
    }
}

// round 12
// speedup vs baseline: 1.6870x; 1.0940x over previous
#include <cuda_runtime.h>
#include <cuda_fp16.h>
#include <math.h>

#define N_NODES 40000
#define E_EDGES 200000
#define DIM 256
#define NHEAD 8
#define NODE_F (N_NODES * DIM)
#define PAD_F (64 * DIM)
#define NSEG (3 * N_NODES)

// ---------------- scratch (device globals) ----------------
__device__ __half g_hrh[2][NODE_F + PAD_F];
__device__ __half g_Qh[2][NODE_F];
__device__ __half g_kh[3][NODE_F];
__device__ __half g_vh[3][NODE_F];
__device__ __half g_WTh[2048 * 256];
__device__ float  g_bc[2048];
__device__ __half g_WaTh[2 * 256 * 256];
__device__ __half g_tth[2][NODE_F + PAD_F];
__device__ int    g_hist[NSEG];               // zero at load; scan3 re-zeroes each run
__device__ int    g_rowptr[NSEG + 1];
__device__ int    g_cursor[NSEG];
__device__ int    g_bsum[512];
__device__ int    g_csr[3 * E_EDGES];

struct Job {
    const __half* A; const __half* W; const float* bias; void* outp;
    const float* Hres; const float* skipv; int cin; int mode;
};
struct Jobs { Job j[16]; };

// ---------------- helpers ----------------
__device__ __forceinline__ unsigned pack2(float a, float b) {
    __half2 h = __floats2half2_rn(a, b);
    return *(unsigned*)&h;
}
__device__ __forceinline__ void mma_f16(float* d, const unsigned* a, const unsigned* b) {
    asm volatile(
        "mma.sync.aligned.m16n8k16.row.col.f32.f16.f16.f32 "
        "{%0,%1,%2,%3}, {%4,%5,%6,%7}, {%8,%9}, {%0,%1,%2,%3};"
        : "+f"(d[0]), "+f"(d[1]), "+f"(d[2]), "+f"(d[3])
        : "r"(a[0]), "r"(a[1]), "r"(a[2]), "r"(a[3]), "r"(b[0]), "r"(b[1]));
}
__device__ __forceinline__ void cpa16(unsigned saddr, const void* g) {
    asm volatile("cp.async.cg.shared.global [%0], [%1], 16;" :: "r"(saddr), "l"(g));
}
__device__ __forceinline__ unsigned smem_u32(const void* p) {
    unsigned a;
    asm("{ .reg .u64 t; cvta.to.shared.u64 t, %1; cvt.u32.u64 %0, t; }" : "=r"(a) : "l"(p));
    return a;
}
__device__ __forceinline__ void ld8h(const __half* p, float* f) {
    uint4 u = *(const uint4*)p;
    float2 a;
    a = __half22float2(*(__half2*)&u.x); f[0] = a.x; f[1] = a.y;
    a = __half22float2(*(__half2*)&u.y); f[2] = a.x; f[3] = a.y;
    a = __half22float2(*(__half2*)&u.z); f[4] = a.x; f[5] = a.y;
    a = __half22float2(*(__half2*)&u.w); f[6] = a.x; f[7] = a.y;
}
// fp16 dot of 8 elements (q packed half2 x4 vs raw uint4 k), returns f32
__device__ __forceinline__ float dot8h(const __half2* qh, uint4 ku) {
    __half2 acc = __hmul2(qh[0], *(__half2*)&ku.x);
    acc = __hfma2(qh[1], *(__half2*)&ku.y, acc);
    acc = __hfma2(qh[2], *(__half2*)&ku.z, acc);
    acc = __hfma2(qh[3], *(__half2*)&ku.w, acc);
    float2 f = __half22float2(acc);
    return f.x + f.y;
}

// ---------------- prep: round inputs + build weights/biases + dst histogram ----------------
#define NGRP  (NODE_F / 16)
#define TOTW  (2048 * 256)
#define TOTB  2048
#define TOTWA (2 * 256 * 256)
#define PREP_BASE (NGRP + TOTW + TOTB + TOTWA)
__device__ __forceinline__ int halfidx(int k) {
    int w = k >> 1, h = k & 1, wi = w & 7;
    int pw = (wi < 4) ? 2 * wi : 2 * wi - 7;
    return ((w >> 3) << 4) + pw * 2 + h;
}
__global__ void prep_kernel(const float* __restrict__ hA, const float* __restrict__ hB,
                            const float* __restrict__ Wq, const float* __restrict__ bq,
                            const float* __restrict__ Wk, const float* __restrict__ bk,
                            const float* __restrict__ Wv, const float* __restrict__ bv,
                            const float* __restrict__ Wa,
                            const float* __restrict__ rel_att, const float* __restrict__ rel_msg,
                            const int* __restrict__ d0, const int* __restrict__ d1,
                            const int* __restrict__ d2, int E) {
    int gid = blockIdx.x * blockDim.x + threadIdx.x;
    if (gid < NGRP) {
        int i = gid;
        #pragma unroll
        for (int t = 0; t < 2; t++) {
            const float* src = t ? hB : hA;
            float4 f0 = ((const float4*)src)[4 * i + 0];
            float4 f1 = ((const float4*)src)[4 * i + 1];
            float4 f2 = ((const float4*)src)[4 * i + 2];
            float4 f3 = ((const float4*)src)[4 * i + 3];
            unsigned W0 = pack2(f0.x, f0.y), W1 = pack2(f0.z, f0.w);
            unsigned W2 = pack2(f1.x, f1.y), W3 = pack2(f1.z, f1.w);
            unsigned W4 = pack2(f2.x, f2.y), W5 = pack2(f2.z, f2.w);
            unsigned W6 = pack2(f3.x, f3.y), W7 = pack2(f3.z, f3.w);
            ((uint4*)g_hrh[t])[2 * i]     = make_uint4(W0, W4, W1, W5);
            ((uint4*)g_hrh[t])[2 * i + 1] = make_uint4(W2, W6, W3, W7);
        }
        return;
    }
    gid -= NGRP;
    if (gid < TOTW) {
        int k = gid & 255;
        int n = gid >> 8;
        int side  = (n < 1280) ? 0 : 1;
        int local = side ? (n - 1280) : n;
        int g = local >> 8, col = local & 255;
        float val;
        if (g == 0) {
            val = Wq[side * 65536 + k * 256 + col];
        } else {
            int r   = side ? 1 : ((g <= 2) ? 0 : 2);
            int isv = side ? (g == 2) : ((g & 1) == 0);
            const float* W  = (isv ? Wv : Wk) + side * 65536 + k * 256 + (col >> 5) * 32;
            const float* rp = (isv ? rel_msg : rel_att) + r * 8192 + (col >> 5) * 1024 + (col & 31);
            float acc = 0.f;
            #pragma unroll
            for (int d = 0; d < 32; d++) acc += W[d] * rp[d * 32];
            val = acc;
        }
        g_WTh[n * 256 + halfidx(k)] = __float2half_rn(val);
        return;
    }
    gid -= TOTW;
    if (gid < TOTB) {
        int n = gid;
        int side  = (n < 1280) ? 0 : 1;
        int local = side ? (n - 1280) : n;
        int g = local >> 8, col = local & 255;
        float val;
        if (g == 0) {
            val = bq[side * 256 + col];
        } else {
            int r   = side ? 1 : ((g <= 2) ? 0 : 2);
            int isv = side ? (g == 2) : ((g & 1) == 0);
            const float* b  = (isv ? bv : bk) + side * 256 + (col >> 5) * 32;
            const float* rp = (isv ? rel_msg : rel_att) + r * 8192 + (col >> 5) * 1024 + (col & 31);
            float acc = 0.f;
            #pragma unroll
            for (int d = 0; d < 32; d++) acc += b[d] * rp[d * 32];
            val = acc;
        }
        g_bc[n] = val;
        return;
    }
    gid -= TOTB;
    if (gid < TOTWA) {
        int i = gid;
        int k = i & 255, nn = (i >> 8) & 255, t = i >> 16;
        g_WaTh[t * 65536 + nn * 256 + halfidx(k)] = __float2half_rn(Wa[t * 65536 + k * 256 + nn]);
        return;
    }
    gid -= TOTWA;
    if (gid < 3 * E) {
        int r = gid / E, e = gid - r * E;
        const int* dd = (r == 0) ? d0 : ((r == 1) ? d1 : d2);
        atomicAdd(&g_hist[r * N_NODES + dd[e]], 1);
    }
}

// ---------------- fp16 mma.sync GEMM, cp.async 2-stage, K-chunks of 64 halves ----------------
#define SSTR32 40
#define STG_WORDS 10240
#define STG_BYTES 40960u
#define TG_SMEM 81920
__global__ void __launch_bounds__(256, 2) tgemm(Jobs jobs, int M) {
    extern __shared__ float smem[];
    unsigned sbase = smem_u32(smem);
    Job jb = jobs.j[blockIdx.x];
    int tid = threadIdx.x, lane = tid & 31, wid = tid >> 5;
    int row0 = blockIdx.y * 128;
    int wm = (wid >> 2) * 64;
    int wn = (wid & 3) * 32;
    int g = lane >> 2, c = lane & 3;

    float acc[4][4][4];
    #pragma unroll
    for (int i = 0; i < 4; i++)
        #pragma unroll
        for (int j = 0; j < 4; j++)
            #pragma unroll
            for (int q = 0; q < 4; q++) acc[i][j][q] = 0.f;

    int r_st[4], jc_st[4];
    #pragma unroll
    for (int i = 0; i < 4; i++) {
        int sl = i * 256 + tid;
        r_st[i] = sl >> 3; jc_st[i] = sl & 7;
    }

    #pragma unroll
    for (int i = 0; i < 4; i++) {
        unsigned so = sbase + (unsigned)(r_st[i] * 160 + jc_st[i] * 16);
        cpa16(so, jb.A + (size_t)(row0 + r_st[i]) * 256 + jc_st[i] * 8);
        cpa16(so + 20480u, jb.W + (size_t)r_st[i] * 256 + jc_st[i] * 8);
    }
    asm volatile("cp.async.commit_group;" ::: "memory");

    #pragma unroll
    for (int ck = 0; ck < 4; ck++) {
        asm volatile("cp.async.wait_group 0;" ::: "memory");
        __syncthreads();
        if (ck + 1 < 4) {
            unsigned stb = sbase + ((ck + 1) & 1) * STG_BYTES;
            #pragma unroll
            for (int i = 0; i < 4; i++) {
                unsigned so = stb + (unsigned)(r_st[i] * 160 + jc_st[i] * 16);
                cpa16(so, jb.A + (size_t)(row0 + r_st[i]) * 256 + (ck + 1) * 64 + jc_st[i] * 8);
                cpa16(so + 20480u, jb.W + (size_t)r_st[i] * 256 + (ck + 1) * 64 + jc_st[i] * 8);
            }
            asm volatile("cp.async.commit_group;" ::: "memory");
        }
        const unsigned* sAw = ((const unsigned*)smem) + (ck & 1) * STG_WORDS;
        const unsigned* sBw = sAw + 5120;
        #pragma unroll
        for (int s = 0; s < 4; s++) {
            unsigned af[4][4], bf[4][2];
            int kc = s * 8 + 2 * c;
            #pragma unroll
            for (int mt = 0; mt < 4; mt++) {
                int m = wm + mt * 16;
                uint2 lo = *(const uint2*)&sAw[(m + g)     * SSTR32 + kc];
                uint2 hi = *(const uint2*)&sAw[(m + g + 8) * SSTR32 + kc];
                af[mt][0] = lo.x; af[mt][1] = hi.x; af[mt][2] = lo.y; af[mt][3] = hi.y;
            }
            #pragma unroll
            for (int nt = 0; nt < 4; nt++) {
                uint2 b = *(const uint2*)&sBw[(wn + nt * 8 + g) * SSTR32 + kc];
                bf[nt][0] = b.x; bf[nt][1] = b.y;
            }
            #pragma unroll
            for (int mt = 0; mt < 4; mt++)
                #pragma unroll
                for (int nt = 0; nt < 4; nt++)
                    mma_f16(acc[mt][nt], af[mt], bf[nt]);
        }
    }

    float alpha = 1.f, beta = 0.f;
    if (jb.mode == 1) {
        float sv = *jb.skipv;
        alpha = 1.f / (1.f + __expf(-sv));
        beta  = 1.f - alpha;
    }
    int cinb = jb.cin + wn;
    #pragma unroll
    for (int mt = 0; mt < 4; mt++) {
        #pragma unroll
        for (int half = 0; half < 2; half++) {
            int row = row0 + wm + mt * 16 + g + half * 8;
            if (row >= M) continue;
            #pragma unroll
            for (int nt = 0; nt < 4; nt++) {
                int lcol = wn + nt * 8 + 2 * c;
                int cin = cinb + nt * 8 + 2 * c;
                float v0 = acc[mt][nt][half * 2 + 0] + jb.bias[lcol];
                float v1 = acc[mt][nt][half * 2 + 1] + jb.bias[lcol + 1];
                if (jb.mode == 1) {
                    float* O = (float*)jb.outp;
                    v0 = v0 * alpha + jb.Hres[(size_t)row * 256 + cin]     * beta;
                    v1 = v1 * alpha + jb.Hres[(size_t)row * 256 + cin + 1] * beta;
                    float2 o; o.x = v0; o.y = v1;
                    *(float2*)(O + (size_t)row * 256 + cin) = o;
                } else {
                    __half* H = (__half*)jb.outp;
                    *(unsigned*)(H + (size_t)row * 256 + cin) = pack2(v0, v1);
                }
            }
        }
    }
}

// ---------------- CSR scans ----------------
__global__ void scan1() {
    __shared__ int sh[256];
    int i = blockIdx.x * 256 + threadIdx.x;
    sh[threadIdx.x] = (i < NSEG) ? g_hist[i] : 0;
    __syncthreads();
    for (int o = 128; o > 0; o >>= 1) {
        if (threadIdx.x < o) sh[threadIdx.x] += sh[threadIdx.x + o];
        __syncthreads();
    }
    if (threadIdx.x == 0) g_bsum[blockIdx.x] = sh[0];
}
__global__ void scan2() {              // parallel exclusive scan of 469 block sums
    __shared__ int sh[512];
    int i = threadIdx.x;
    int v = (i < 469) ? g_bsum[i] : 0;
    sh[i] = v;
    __syncthreads();
    #pragma unroll
    for (int o = 1; o < 512; o <<= 1) {
        int t = (i >= o) ? sh[i - o] : 0;
        __syncthreads();
        sh[i] += t;
        __syncthreads();
    }
    if (i < 469) g_bsum[i] = sh[i] - v;   // exclusive
    if (i == 0)  g_rowptr[NSEG] = sh[468];
}
__global__ void scan3() {
    __shared__ int sh[256];
    int i = blockIdx.x * 256 + threadIdx.x;
    int v = (i < NSEG) ? g_hist[i] : 0;
    sh[threadIdx.x] = v;
    __syncthreads();
    for (int o = 1; o < 256; o <<= 1) {
        int t = (threadIdx.x >= (unsigned)o) ? sh[threadIdx.x - o] : 0;
        __syncthreads();
        sh[threadIdx.x] += t;
        __syncthreads();
    }
    int excl = sh[threadIdx.x] - v + g_bsum[blockIdx.x];
    if (i < NSEG) {
        g_rowptr[i] = excl;
        g_cursor[i] = excl;
        g_hist[i] = 0;                 // restore for next graph replay
    }
}
__global__ void scatter_kernel(const int* __restrict__ s0, const int* __restrict__ d0,
                               const int* __restrict__ s1, const int* __restrict__ d1,
                               const int* __restrict__ s2, const int* __restrict__ d2, int E) {
    int i = blockIdx.x * blockDim.x + threadIdx.x;
    if (i >= 3 * E) return;
    int r = i / E, e = i - r * E;
    const int* ss = (r == 0) ? s0 : ((r == 1) ? s1 : s2);
    const int* dd = (r == 0) ? d0 : ((r == 1) ? d1 : d2);
    int pos = atomicAdd(&g_cursor[r * N_NODES + dd[e]], 1);
    g_csr[pos] = ss[e];
}

// ---------------- aggregation: warp per (type, dst), half2 score dot, unroll x2 ----------------
__global__ void agg_kernel(const float* __restrict__ rel_pri) {
    int gw = (blockIdx.x * blockDim.x + threadIdx.x) >> 5;
    int lane = threadIdx.x & 31;
    if (gw >= 2 * N_NODES) return;
    int t = (gw >= N_NODES) ? 1 : 0;
    int n = gw - t * N_NODES;
    const float rs = 0.17677669529663687f;
    int head = lane >> 2;

    uint4 qu = *(const uint4*)(g_Qh[t] + (size_t)n * DIM + 8 * lane);
    __half2 qh[4] = {*(__half2*)&qu.x, *(__half2*)&qu.y, *(__half2*)&qu.z, *(__half2*)&qu.w};

    float outv[8];
    #pragma unroll
    for (int j = 0; j < 8; j++) outv[j] = 0.f;

    int rfirst = t ? 0 : 1;
    int rcount = t ? 1 : 2;
    float scale = t ? 1.f : 0.5f;

    for (int ri = 0; ri < rcount; ri++) {
        int r = rfirst + ri;
        float pr = rel_pri[r * NHEAD + head] * rs;
        int seg = r * N_NODES + n;
        int beg = g_rowptr[seg], end = g_rowptr[seg + 1];
        const __half* Kb = g_kh[r];
        const __half* Vb = g_vh[r];
        float a[8];
        #pragma unroll
        for (int j = 0; j < 8; j++) a[j] = 0.f;
        float ssum = 0.f;
        int i = beg;
        for (; i + 1 < end; i += 2) {
            int sn0 = g_csr[i], sn1 = g_csr[i + 1];
            uint4 k0 = *(const uint4*)(Kb + (size_t)sn0 * DIM + 8 * lane);
            uint4 k1 = *(const uint4*)(Kb + (size_t)sn1 * DIM + 8 * lane);
            float v0[8], v1[8];
            ld8h(Vb + (size_t)sn0 * DIM + 8 * lane, v0);
            ld8h(Vb + (size_t)sn1 * DIM + 8 * lane, v1);
            float p0 = dot8h(qh, k0);
            float p1 = dot8h(qh, k1);
            p0 += __shfl_xor_sync(0xffffffffu, p0, 2);
            p1 += __shfl_xor_sync(0xffffffffu, p1, 2);
            p0 += __shfl_xor_sync(0xffffffffu, p0, 1);
            p1 += __shfl_xor_sync(0xffffffffu, p1, 1);
            float ex0 = __expf(p0 * pr);
            float ex1 = __expf(p1 * pr);
            ssum += ex0 + ex1;
            #pragma unroll
            for (int j = 0; j < 8; j++) a[j] += ex0 * v0[j] + ex1 * v1[j];
        }
        if (i < end) {
            int sn = g_csr[i];
            uint4 kk = *(const uint4*)(Kb + (size_t)sn * DIM + 8 * lane);
            float vv[8];
            ld8h(Vb + (size_t)sn * DIM + 8 * lane, vv);
            float p = dot8h(qh, kk);
            p += __shfl_xor_sync(0xffffffffu, p, 2);
            p += __shfl_xor_sync(0xffffffffu, p, 1);
            float ex = __expf(p * pr);
            ssum += ex;
            #pragma unroll
            for (int j = 0; j < 8; j++) a[j] += ex * vv[j];
        }
        float inv = (ssum > 0.f) ? scale / ssum : 0.f;
        #pragma unroll
        for (int j = 0; j < 8; j++) outv[j] += a[j] * inv;
    }

    unsigned* orow = (unsigned*)(g_tth[t] + (size_t)n * DIM);
    #pragma unroll
    for (int j = 0; j < 4; j++) {
        int w = 4 * lane + j;
        int wi = w & 7;
        int pos = (w & ~7) + ((wi < 4) ? 2 * wi : 2 * wi - 7);
        orow[pos] = pack2(outv[2 * j], outv[2 * j + 1]);
    }
}

// ---------------- launch ----------------
extern "C" void kernel_launch(void* const* d_in, const int* in_sizes, int n_in,
                              void* d_out, int out_size) {
    const float* h_A     = (const float*)d_in[0];
    const float* h_B     = (const float*)d_in[1];
    const float* Wk      = (const float*)d_in[2];
    const float* bk      = (const float*)d_in[3];
    const float* Wq      = (const float*)d_in[4];
    const float* bq      = (const float*)d_in[5];
    const float* Wv      = (const float*)d_in[6];
    const float* bv      = (const float*)d_in[7];
    const float* Wa      = (const float*)d_in[8];
    const float* ba      = (const float*)d_in[9];
    const float* rel_att = (const float*)d_in[10];
    const float* rel_msg = (const float*)d_in[11];
    const float* rel_pri = (const float*)d_in[12];
    const float* skip    = (const float*)d_in[13];
    const int*   src[3]  = {(const int*)d_in[14], (const int*)d_in[16], (const int*)d_in[18]};
    const int*   dst[3]  = {(const int*)d_in[15], (const int*)d_in[17], (const int*)d_in[19]};
    const int E = in_sizes[14];
    float* out = (float*)d_out;

    __half *pHr[2], *pQh[2], *pkh[3], *pvh[3], *pWTh, *pWaTh, *ptt[2];
    float *pbc;
    {
        void* base;
        cudaGetSymbolAddress(&base, g_hrh);  pHr[0] = (__half*)base; pHr[1] = (__half*)base + NODE_F + PAD_F;
        cudaGetSymbolAddress(&base, g_Qh);   pQh[0] = (__half*)base; pQh[1] = (__half*)base + NODE_F;
        cudaGetSymbolAddress(&base, g_kh);   for (int r = 0; r < 3; r++) pkh[r] = (__half*)base + (size_t)r * NODE_F;
        cudaGetSymbolAddress(&base, g_vh);   for (int r = 0; r < 3; r++) pvh[r] = (__half*)base + (size_t)r * NODE_F;
        cudaGetSymbolAddress(&base, g_WTh);  pWTh = (__half*)base;
        cudaGetSymbolAddress(&base, g_bc);   pbc = (float*)base;
        cudaGetSymbolAddress(&base, g_WaTh); pWaTh = (__half*)base;
        cudaGetSymbolAddress(&base, g_tth);  ptt[0] = (__half*)base; ptt[1] = (__half*)base + NODE_F + PAD_F;
    }

    cudaFuncSetAttribute(tgemm, cudaFuncAttributeMaxDynamicSharedMemorySize, TG_SMEM);

    // prep (round + weight build + dst histogram, merged)
    {
        int tot = PREP_BASE + 3 * E;
        prep_kernel<<<(tot + 255) / 256, 256>>>(h_A, h_B, Wq, bq, Wk, bk, Wv, bv, Wa,
                                                rel_att, rel_msg, dst[0], dst[1], dst[2], E);
    }

    // CSR scans + scatter
    scan1<<<469, 256>>>();
    scan2<<<1, 512>>>();
    scan3<<<469, 256>>>();
    scatter_kernel<<<(3 * E + 255) / 256, 256>>>(src[0], dst[0], src[1], dst[1], src[2], dst[2], E);

    int mblocks = (N_NODES + 127) / 128;

    // merged projection GEMMs: 16 column-tiles -> fp16 outputs
    {
        Jobs jobs;
        __half* targA[5] = {pQh[0], pkh[0], pvh[0], pkh[2], pvh[2]};
        __half* targB[3] = {pQh[1], pkh[1], pvh[1]};
        for (int x = 0; x < 10; x++) {
            int col0 = x * 128;
            jobs.j[x] = { pHr[0], pWTh + (size_t)col0 * 256, pbc + col0,
                          (void*)targA[x >> 1], nullptr, nullptr, (x & 1) * 128, 0 };
        }
        for (int x2 = 0; x2 < 6; x2++) {
            int col0 = 1280 + x2 * 128;
            jobs.j[10 + x2] = { pHr[1], pWTh + (size_t)col0 * 256, pbc + col0,
                                (void*)targB[x2 >> 1], nullptr, nullptr, (x2 & 1) * 128, 0 };
        }
        dim3 grid(16, mblocks);
        tgemm<<<grid, 256, TG_SMEM>>>(jobs, N_NODES);
    }

    // warp-per-(type,dst) aggregation, writes g_tth directly
    {
        int nwarp_blocks = (2 * N_NODES * 32 + 255) / 256;
        agg_kernel<<<nwarp_blocks, 256>>>(rel_pri);
    }

    // merged output GEMMs with fused skip epilogue (f32 out)
    {
        Jobs jobs;
        for (int x = 0; x < 2; x++)
            jobs.j[x] = { ptt[0], pWaTh + (size_t)x * 128 * 256, ba + x * 128,
                          (void*)out, h_A, skip, x * 128, 1 };
        for (int x = 0; x < 2; x++)
            jobs.j[2 + x] = { ptt[1], pWaTh + 65536 + (size_t)x * 128 * 256, ba + 256 + x * 128,
                              (void*)(out + NODE_F), h_B, skip + 1, x * 128, 1 };
        dim3 grid(4, mblocks);
        tgemm<<<grid, 256, TG_SMEM>>>(jobs, N_NODES);
    }
}

// round 13
// speedup vs baseline: 1.7072x; 1.0119x over previous
#include <cuda_runtime.h>
#include <cuda_fp16.h>
#include <math.h>

#define N_NODES 40000
#define E_EDGES 200000
#define DIM 256
#define NHEAD 8
#define NODE_F (N_NODES * DIM)
#define PAD_F (64 * DIM)
#define NSEG (3 * N_NODES)

// ---------------- scratch (device globals) ----------------
__device__ __half g_hrh[2][NODE_F + PAD_F];
__device__ __half g_Qh[2][NODE_F];
__device__ __half g_kh[3][NODE_F];
__device__ __half g_vh[3][NODE_F];
__device__ __half g_WTh[2048 * 256];
__device__ float  g_bc[2048];
__device__ __half g_WaTh[2 * 256 * 256];
__device__ __half g_tth[2][NODE_F + PAD_F];
__device__ int    g_hist[NSEG];               // zero at load; scan re-zeroes each run
__device__ int    g_rowptr[NSEG];
__device__ int    g_cursor[NSEG];             // after scatter: cursor[seg] == segment end
__device__ int    g_total;                    // zero at load; scatter re-zeroes each run
__device__ int    g_csr[3 * E_EDGES];

struct Job {
    const __half* A; const __half* W; const float* bias; void* outp;
    const float* Hres; const float* skipv; int cin; int mode;
};
struct Jobs { Job j[16]; };

// ---------------- helpers ----------------
__device__ __forceinline__ unsigned pack2(float a, float b) {
    __half2 h = __floats2half2_rn(a, b);
    return *(unsigned*)&h;
}
__device__ __forceinline__ void mma_f16(float* d, const unsigned* a, const unsigned* b) {
    asm volatile(
        "mma.sync.aligned.m16n8k16.row.col.f32.f16.f16.f32 "
        "{%0,%1,%2,%3}, {%4,%5,%6,%7}, {%8,%9}, {%0,%1,%2,%3};"
        : "+f"(d[0]), "+f"(d[1]), "+f"(d[2]), "+f"(d[3])
        : "r"(a[0]), "r"(a[1]), "r"(a[2]), "r"(a[3]), "r"(b[0]), "r"(b[1]));
}
__device__ __forceinline__ void cpa16(unsigned saddr, const void* g) {
    asm volatile("cp.async.cg.shared.global [%0], [%1], 16;" :: "r"(saddr), "l"(g));
}
__device__ __forceinline__ unsigned smem_u32(const void* p) {
    unsigned a;
    asm("{ .reg .u64 t; cvta.to.shared.u64 t, %1; cvt.u32.u64 %0, t; }" : "=r"(a) : "l"(p));
    return a;
}
__device__ __forceinline__ void ld8h_nc(const __half* p, float* f) {
    uint4 u = __ldg((const uint4*)p);
    float2 a;
    a = __half22float2(*(__half2*)&u.x); f[0] = a.x; f[1] = a.y;
    a = __half22float2(*(__half2*)&u.y); f[2] = a.x; f[3] = a.y;
    a = __half22float2(*(__half2*)&u.z); f[4] = a.x; f[5] = a.y;
    a = __half22float2(*(__half2*)&u.w); f[6] = a.x; f[7] = a.y;
}
__device__ __forceinline__ float dot8h(const __half2* qh, uint4 ku) {
    __half2 acc = __hmul2(qh[0], *(__half2*)&ku.x);
    acc = __hfma2(qh[1], *(__half2*)&ku.y, acc);
    acc = __hfma2(qh[2], *(__half2*)&ku.z, acc);
    acc = __hfma2(qh[3], *(__half2*)&ku.w, acc);
    float2 f = __half22float2(acc);
    return f.x + f.y;
}

// ---------------- prep: round inputs + build weights/biases + dst histogram ----------------
#define NGRP  (NODE_F / 16)
#define TOTW  (2048 * 256)
#define TOTB  2048
#define TOTWA (2 * 256 * 256)
#define PREP_BASE (NGRP + TOTW + TOTB + TOTWA)
__device__ __forceinline__ int halfidx(int k) {
    int w = k >> 1, h = k & 1, wi = w & 7;
    int pw = (wi < 4) ? 2 * wi : 2 * wi - 7;
    return ((w >> 3) << 4) + pw * 2 + h;
}
__global__ void prep_kernel(const float* __restrict__ hA, const float* __restrict__ hB,
                            const float* __restrict__ Wq, const float* __restrict__ bq,
                            const float* __restrict__ Wk, const float* __restrict__ bk,
                            const float* __restrict__ Wv, const float* __restrict__ bv,
                            const float* __restrict__ Wa,
                            const float* __restrict__ rel_att, const float* __restrict__ rel_msg,
                            const int* __restrict__ d0, const int* __restrict__ d1,
                            const int* __restrict__ d2, int E) {
    int gid = blockIdx.x * blockDim.x + threadIdx.x;
    if (gid < NGRP) {
        int i = gid;
        #pragma unroll
        for (int t = 0; t < 2; t++) {
            const float* src = t ? hB : hA;
            float4 f0 = ((const float4*)src)[4 * i + 0];
            float4 f1 = ((const float4*)src)[4 * i + 1];
            float4 f2 = ((const float4*)src)[4 * i + 2];
            float4 f3 = ((const float4*)src)[4 * i + 3];
            unsigned W0 = pack2(f0.x, f0.y), W1 = pack2(f0.z, f0.w);
            unsigned W2 = pack2(f1.x, f1.y), W3 = pack2(f1.z, f1.w);
            unsigned W4 = pack2(f2.x, f2.y), W5 = pack2(f2.z, f2.w);
            unsigned W6 = pack2(f3.x, f3.y), W7 = pack2(f3.z, f3.w);
            ((uint4*)g_hrh[t])[2 * i]     = make_uint4(W0, W4, W1, W5);
            ((uint4*)g_hrh[t])[2 * i + 1] = make_uint4(W2, W6, W3, W7);
        }
        return;
    }
    gid -= NGRP;
    if (gid < TOTW) {
        int k = gid & 255;
        int n = gid >> 8;
        int side  = (n < 1280) ? 0 : 1;
        int local = side ? (n - 1280) : n;
        int g = local >> 8, col = local & 255;
        float val;
        if (g == 0) {
            val = Wq[side * 65536 + k * 256 + col];
        } else {
            int r   = side ? 1 : ((g <= 2) ? 0 : 2);
            int isv = side ? (g == 2) : ((g & 1) == 0);
            const float* W  = (isv ? Wv : Wk) + side * 65536 + k * 256 + (col >> 5) * 32;
            const float* rp = (isv ? rel_msg : rel_att) + r * 8192 + (col >> 5) * 1024 + (col & 31);
            float acc = 0.f;
            #pragma unroll
            for (int d = 0; d < 32; d++) acc += W[d] * rp[d * 32];
            val = acc;
        }
        g_WTh[n * 256 + halfidx(k)] = __float2half_rn(val);
        return;
    }
    gid -= TOTW;
    if (gid < TOTB) {
        int n = gid;
        int side  = (n < 1280) ? 0 : 1;
        int local = side ? (n - 1280) : n;
        int g = local >> 8, col = local & 255;
        float val;
        if (g == 0) {
            val = bq[side * 256 + col];
        } else {
            int r   = side ? 1 : ((g <= 2) ? 0 : 2);
            int isv = side ? (g == 2) : ((g & 1) == 0);
            const float* b  = (isv ? bv : bk) + side * 256 + (col >> 5) * 32;
            const float* rp = (isv ? rel_msg : rel_att) + r * 8192 + (col >> 5) * 1024 + (col & 31);
            float acc = 0.f;
            #pragma unroll
            for (int d = 0; d < 32; d++) acc += b[d] * rp[d * 32];
            val = acc;
        }
        g_bc[n] = val;
        return;
    }
    gid -= TOTB;
    if (gid < TOTWA) {
        int i = gid;
        int k = i & 255, nn = (i >> 8) & 255, t = i >> 16;
        g_WaTh[t * 65536 + nn * 256 + halfidx(k)] = __float2half_rn(Wa[t * 65536 + k * 256 + nn]);
        return;
    }
    gid -= TOTWA;
    if (gid < 3 * E) {
        int r = gid / E, e = gid - r * E;
        const int* dd = (r == 0) ? d0 : ((r == 1) ? d1 : d2);
        atomicAdd(&g_hist[r * N_NODES + dd[e]], 1);
    }
}

// ---------------- fp16 mma.sync GEMM, cp.async 2-stage, K-chunks of 64 halves ----------------
#define SSTR32 40
#define STG_WORDS 10240
#define STG_BYTES 40960u
#define TG_SMEM 81920
__global__ void __launch_bounds__(256, 2) tgemm(Jobs jobs, int M) {
    extern __shared__ float smem[];
    unsigned sbase = smem_u32(smem);
    Job jb = jobs.j[blockIdx.x];
    int tid = threadIdx.x, lane = tid & 31, wid = tid >> 5;
    int row0 = blockIdx.y * 128;
    int wm = (wid >> 2) * 64;
    int wn = (wid & 3) * 32;
    int g = lane >> 2, c = lane & 3;

    float acc[4][4][4];
    #pragma unroll
    for (int i = 0; i < 4; i++)
        #pragma unroll
        for (int j = 0; j < 4; j++)
            #pragma unroll
            for (int q = 0; q < 4; q++) acc[i][j][q] = 0.f;

    int r_st[4], jc_st[4];
    #pragma unroll
    for (int i = 0; i < 4; i++) {
        int sl = i * 256 + tid;
        r_st[i] = sl >> 3; jc_st[i] = sl & 7;
    }

    #pragma unroll
    for (int i = 0; i < 4; i++) {
        unsigned so = sbase + (unsigned)(r_st[i] * 160 + jc_st[i] * 16);
        cpa16(so, jb.A + (size_t)(row0 + r_st[i]) * 256 + jc_st[i] * 8);
        cpa16(so + 20480u, jb.W + (size_t)r_st[i] * 256 + jc_st[i] * 8);
    }
    asm volatile("cp.async.commit_group;" ::: "memory");

    #pragma unroll
    for (int ck = 0; ck < 4; ck++) {
        asm volatile("cp.async.wait_group 0;" ::: "memory");
        __syncthreads();
        if (ck + 1 < 4) {
            unsigned stb = sbase + ((ck + 1) & 1) * STG_BYTES;
            #pragma unroll
            for (int i = 0; i < 4; i++) {
                unsigned so = stb + (unsigned)(r_st[i] * 160 + jc_st[i] * 16);
                cpa16(so, jb.A + (size_t)(row0 + r_st[i]) * 256 + (ck + 1) * 64 + jc_st[i] * 8);
                cpa16(so + 20480u, jb.W + (size_t)r_st[i] * 256 + (ck + 1) * 64 + jc_st[i] * 8);
            }
            asm volatile("cp.async.commit_group;" ::: "memory");
        }
        const unsigned* sAw = ((const unsigned*)smem) + (ck & 1) * STG_WORDS;
        const unsigned* sBw = sAw + 5120;
        #pragma unroll
        for (int s = 0; s < 4; s++) {
            unsigned af[4][4], bf[4][2];
            int kc = s * 8 + 2 * c;
            #pragma unroll
            for (int mt = 0; mt < 4; mt++) {
                int m = wm + mt * 16;
                uint2 lo = *(const uint2*)&sAw[(m + g)     * SSTR32 + kc];
                uint2 hi = *(const uint2*)&sAw[(m + g + 8) * SSTR32 + kc];
                af[mt][0] = lo.x; af[mt][1] = hi.x; af[mt][2] = lo.y; af[mt][3] = hi.y;
            }
            #pragma unroll
            for (int nt = 0; nt < 4; nt++) {
                uint2 b = *(const uint2*)&sBw[(wn + nt * 8 + g) * SSTR32 + kc];
                bf[nt][0] = b.x; bf[nt][1] = b.y;
            }
            #pragma unroll
            for (int mt = 0; mt < 4; mt++)
                #pragma unroll
                for (int nt = 0; nt < 4; nt++)
                    mma_f16(acc[mt][nt], af[mt], bf[nt]);
        }
    }

    float alpha = 1.f, beta = 0.f;
    if (jb.mode == 1) {
        float sv = *jb.skipv;
        alpha = 1.f / (1.f + __expf(-sv));
        beta  = 1.f - alpha;
    }
    int cinb = jb.cin + wn;
    #pragma unroll
    for (int mt = 0; mt < 4; mt++) {
        #pragma unroll
        for (int half = 0; half < 2; half++) {
            int row = row0 + wm + mt * 16 + g + half * 8;
            if (row >= M) continue;
            #pragma unroll
            for (int nt = 0; nt < 4; nt++) {
                int lcol = wn + nt * 8 + 2 * c;
                int cin = cinb + nt * 8 + 2 * c;
                float v0 = acc[mt][nt][half * 2 + 0] + jb.bias[lcol];
                float v1 = acc[mt][nt][half * 2 + 1] + jb.bias[lcol + 1];
                if (jb.mode == 1) {
                    float* O = (float*)jb.outp;
                    v0 = v0 * alpha + jb.Hres[(size_t)row * 256 + cin]     * beta;
                    v1 = v1 * alpha + jb.Hres[(size_t)row * 256 + cin + 1] * beta;
                    float2 o; o.x = v0; o.y = v1;
                    *(float2*)(O + (size_t)row * 256 + cin) = o;
                } else {
                    __half* H = (__half*)jb.outp;
                    *(unsigned*)(H + (size_t)row * 256 + cin) = pack2(v0, v1);
                }
            }
        }
    }
}

// ---------------- single-pass CSR scan: local scan + atomic block base ----------------
// Segment regions are contiguous/disjoint but NOT monotone in segment id — valid for CSR.
__global__ void scan_kernel() {
    __shared__ int sh[256];
    __shared__ int base;
    int i = blockIdx.x * 256 + threadIdx.x;
    int v = (i < NSEG) ? g_hist[i] : 0;
    sh[threadIdx.x] = v;
    __syncthreads();
    for (int o = 1; o < 256; o <<= 1) {
        int t = (threadIdx.x >= (unsigned)o) ? sh[threadIdx.x - o] : 0;
        __syncthreads();
        sh[threadIdx.x] += t;
        __syncthreads();
    }
    if (threadIdx.x == 255) base = atomicAdd(&g_total, sh[255]);
    __syncthreads();
    int excl = sh[threadIdx.x] - v + base;
    if (i < NSEG) {
        g_rowptr[i] = excl;
        g_cursor[i] = excl;
        g_hist[i] = 0;                 // restore for next graph replay
    }
}
__global__ void scatter_kernel(const int* __restrict__ s0, const int* __restrict__ d0,
                               const int* __restrict__ s1, const int* __restrict__ d1,
                               const int* __restrict__ s2, const int* __restrict__ d2, int E) {
    int i = blockIdx.x * blockDim.x + threadIdx.x;
    if (i == 0) g_total = 0;           // restore for next graph replay
    if (i >= 3 * E) return;
    int r = i / E, e = i - r * E;
    const int* ss = (r == 0) ? s0 : ((r == 1) ? s1 : s2);
    const int* dd = (r == 0) ? d0 : ((r == 1) ? d1 : d2);
    int pos = atomicAdd(&g_cursor[r * N_NODES + dd[e]], 1);
    g_csr[pos] = ss[e];
}

// ---------------- aggregation: warp per (type, dst); end pointer = post-scatter cursor ----------------
__global__ void agg_kernel(const float* __restrict__ rel_pri) {
    int gw = (blockIdx.x * blockDim.x + threadIdx.x) >> 5;
    int lane = threadIdx.x & 31;
    if (gw >= 2 * N_NODES) return;
    int t = (gw >= N_NODES) ? 1 : 0;
    int n = gw - t * N_NODES;
    const float rs = 0.17677669529663687f;
    int head = lane >> 2;

    uint4 qu = __ldg((const uint4*)(g_Qh[t] + (size_t)n * DIM + 8 * lane));
    __half2 qh[4] = {*(__half2*)&qu.x, *(__half2*)&qu.y, *(__half2*)&qu.z, *(__half2*)&qu.w};

    float outv[8];
    #pragma unroll
    for (int j = 0; j < 8; j++) outv[j] = 0.f;

    int rfirst = t ? 0 : 1;
    int rcount = t ? 1 : 2;
    float scale = t ? 1.f : 0.5f;

    for (int ri = 0; ri < rcount; ri++) {
        int r = rfirst + ri;
        float pr = rel_pri[r * NHEAD + head] * rs;
        int seg = r * N_NODES + n;
        int beg = g_rowptr[seg], end = g_cursor[seg];   // cursor == segment end after scatter
        const __half* Kb = g_kh[r];
        const __half* Vb = g_vh[r];
        float a[8];
        #pragma unroll
        for (int j = 0; j < 8; j++) a[j] = 0.f;
        float ssum = 0.f;
        int i = beg;
        for (; i + 1 < end; i += 2) {
            int sn0 = __ldg(&g_csr[i]), sn1 = __ldg(&g_csr[i + 1]);
            uint4 k0 = __ldg((const uint4*)(Kb + (size_t)sn0 * DIM + 8 * lane));
            uint4 k1 = __ldg((const uint4*)(Kb + (size_t)sn1 * DIM + 8 * lane));
            float v0[8], v1[8];
            ld8h_nc(Vb + (size_t)sn0 * DIM + 8 * lane, v0);
            ld8h_nc(Vb + (size_t)sn1 * DIM + 8 * lane, v1);
            float p0 = dot8h(qh, k0);
            float p1 = dot8h(qh, k1);
            p0 += __shfl_xor_sync(0xffffffffu, p0, 2);
            p1 += __shfl_xor_sync(0xffffffffu, p1, 2);
            p0 += __shfl_xor_sync(0xffffffffu, p0, 1);
            p1 += __shfl_xor_sync(0xffffffffu, p1, 1);
            float ex0 = __expf(p0 * pr);
            float ex1 = __expf(p1 * pr);
            ssum += ex0 + ex1;
            #pragma unroll
            for (int j = 0; j < 8; j++) a[j] += ex0 * v0[j] + ex1 * v1[j];
        }
        if (i < end) {
            int sn = __ldg(&g_csr[i]);
            uint4 kk = __ldg((const uint4*)(Kb + (size_t)sn * DIM + 8 * lane));
            float vv[8];
            ld8h_nc(Vb + (size_t)sn * DIM + 8 * lane, vv);
            float p = dot8h(qh, kk);
            p += __shfl_xor_sync(0xffffffffu, p, 2);
            p += __shfl_xor_sync(0xffffffffu, p, 1);
            float ex = __expf(p * pr);
            ssum += ex;
            #pragma unroll
            for (int j = 0; j < 8; j++) a[j] += ex * vv[j];
        }
        float inv = (ssum > 0.f) ? scale / ssum : 0.f;
        #pragma unroll
        for (int j = 0; j < 8; j++) outv[j] += a[j] * inv;
    }

    unsigned* orow = (unsigned*)(g_tth[t] + (size_t)n * DIM);
    #pragma unroll
    for (int j = 0; j < 4; j++) {
        int w = 4 * lane + j;
        int wi = w & 7;
        int pos = (w & ~7) + ((wi < 4) ? 2 * wi : 2 * wi - 7);
        orow[pos] = pack2(outv[2 * j], outv[2 * j + 1]);
    }
}

// ---------------- launch ----------------
extern "C" void kernel_launch(void* const* d_in, const int* in_sizes, int n_in,
                              void* d_out, int out_size) {
    const float* h_A     = (const float*)d_in[0];
    const float* h_B     = (const float*)d_in[1];
    const float* Wk      = (const float*)d_in[2];
    const float* bk      = (const float*)d_in[3];
    const float* Wq      = (const float*)d_in[4];
    const float* bq      = (const float*)d_in[5];
    const float* Wv      = (const float*)d_in[6];
    const float* bv      = (const float*)d_in[7];
    const float* Wa      = (const float*)d_in[8];
    const float* ba      = (const float*)d_in[9];
    const float* rel_att = (const float*)d_in[10];
    const float* rel_msg = (const float*)d_in[11];
    const float* rel_pri = (const float*)d_in[12];
    const float* skip    = (const float*)d_in[13];
    const int*   src[3]  = {(const int*)d_in[14], (const int*)d_in[16], (const int*)d_in[18]};
    const int*   dst[3]  = {(const int*)d_in[15], (const int*)d_in[17], (const int*)d_in[19]};
    const int E = in_sizes[14];
    float* out = (float*)d_out;

    __half *pHr[2], *pQh[2], *pkh[3], *pvh[3], *pWTh, *pWaTh, *ptt[2];
    float *pbc;
    {
        void* base;
        cudaGetSymbolAddress(&base, g_hrh);  pHr[0] = (__half*)base; pHr[1] = (__half*)base + NODE_F + PAD_F;
        cudaGetSymbolAddress(&base, g_Qh);   pQh[0] = (__half*)base; pQh[1] = (__half*)base + NODE_F;
        cudaGetSymbolAddress(&base, g_kh);   for (int r = 0; r < 3; r++) pkh[r] = (__half*)base + (size_t)r * NODE_F;
        cudaGetSymbolAddress(&base, g_vh);   for (int r = 0; r < 3; r++) pvh[r] = (__half*)base + (size_t)r * NODE_F;
        cudaGetSymbolAddress(&base, g_WTh);  pWTh = (__half*)base;
        cudaGetSymbolAddress(&base, g_bc);   pbc = (float*)base;
        cudaGetSymbolAddress(&base, g_WaTh); pWaTh = (__half*)base;
        cudaGetSymbolAddress(&base, g_tth);  ptt[0] = (__half*)base; ptt[1] = (__half*)base + NODE_F + PAD_F;
    }

    cudaFuncSetAttribute(tgemm, cudaFuncAttributeMaxDynamicSharedMemorySize, TG_SMEM);

    // prep (round + weight build + dst histogram, merged)
    {
        int tot = PREP_BASE + 3 * E;
        prep_kernel<<<(tot + 255) / 256, 256>>>(h_A, h_B, Wq, bq, Wk, bk, Wv, bv, Wa,
                                                rel_att, rel_msg, dst[0], dst[1], dst[2], E);
    }

    // single-pass CSR scan + scatter
    scan_kernel<<<(NSEG + 255) / 256, 256>>>();
    scatter_kernel<<<(3 * E + 255) / 256, 256>>>(src[0], dst[0], src[1], dst[1], src[2], dst[2], E);

    int mblocks = (N_NODES + 127) / 128;

    // merged projection GEMMs: 16 column-tiles -> fp16 outputs
    {
        Jobs jobs;
        __half* targA[5] = {pQh[0], pkh[0], pvh[0], pkh[2], pvh[2]};
        __half* targB[3] = {pQh[1], pkh[1], pvh[1]};
        for (int x = 0; x < 10; x++) {
            int col0 = x * 128;
            jobs.j[x] = { pHr[0], pWTh + (size_t)col0 * 256, pbc + col0,
                          (void*)targA[x >> 1], nullptr, nullptr, (x & 1) * 128, 0 };
        }
        for (int x2 = 0; x2 < 6; x2++) {
            int col0 = 1280 + x2 * 128;
            jobs.j[10 + x2] = { pHr[1], pWTh + (size_t)col0 * 256, pbc + col0,
                                (void*)targB[x2 >> 1], nullptr, nullptr, (x2 & 1) * 128, 0 };
        }
        dim3 grid(16, mblocks);
        tgemm<<<grid, 256, TG_SMEM>>>(jobs, N_NODES);
    }

    // warp-per-(type,dst) aggregation, writes g_tth directly
    {
        int nwarp_blocks = (2 * N_NODES * 32 + 255) / 256;
        agg_kernel<<<nwarp_blocks, 256>>>(rel_pri);
    }

    // merged output GEMMs with fused skip epilogue (f32 out)
    {
        Jobs jobs;
        for (int x = 0; x < 2; x++)
            jobs.j[x] = { ptt[0], pWaTh + (size_t)x * 128 * 256, ba + x * 128,
                          (void*)out, h_A, skip, x * 128, 1 };
        for (int x = 0; x < 2; x++)
            jobs.j[2 + x] = { ptt[1], pWaTh + 65536 + (size_t)x * 128 * 256, ba + 256 + x * 128,
                              (void*)(out + NODE_F), h_B, skip + 1, x * 128, 1 };
        dim3 grid(4, mblocks);
        tgemm<<<grid, 256, TG_SMEM>>>(jobs, N_NODES);
    }
}